// round 5
// baseline (speedup 1.0000x reference)
#include <cuda_runtime.h>
#include <cuda_bf16.h>

#define BATCH  512
#define N_NODE 200
#define C_IN   200
#define HIDDEN 128

// scratch: xw = x @ W1, [BATCH, N_NODE, HIDDEN] fp32 (52.4 MB)
__device__ float g_xw[(size_t)BATCH * N_NODE * HIDDEN];

// ---------------------------------------------------------------------------
// K1: xw = x @ W1.   x viewed as [M=BATCH*N_NODE, 200], W1 [200,128].
// 128x128 tile per CTA, K-step 8, 256 threads, 8x8 register tile per thread.
// ---------------------------------------------------------------------------
__global__ __launch_bounds__(256) void gemm_xw_kernel(
    const float* __restrict__ x, const float* __restrict__ W1)
{
    __shared__ float xs[8][136];        // [kk][m], padded pitch
    __shared__ float ws[8][128];        // [kk][n]

    const int m0 = blockIdx.x * 128;
    const int t  = threadIdx.x;
    const int tx = t & 15;              // 16 col groups * 8 cols
    const int ty = t >> 4;              // 16 row groups * 8 rows

    // load indices
    const int xm = t >> 1;              // 0..127
    const int xk = (t & 1) * 4;         // 0 or 4
    const int wk = t >> 5;              // 0..7
    const int wn = (t & 31) * 4;        // 0..124

    float acc[8][8];
#pragma unroll
    for (int r = 0; r < 8; r++)
#pragma unroll
        for (int c = 0; c < 8; c++) acc[r][c] = 0.f;

    for (int k0 = 0; k0 < C_IN; k0 += 8) {
        float4 xv = *(const float4*)&x[(size_t)(m0 + xm) * C_IN + k0 + xk];
        xs[xk + 0][xm] = xv.x;
        xs[xk + 1][xm] = xv.y;
        xs[xk + 2][xm] = xv.z;
        xs[xk + 3][xm] = xv.w;
        *(float4*)&ws[wk][wn] = *(const float4*)&W1[(k0 + wk) * HIDDEN + wn];
        __syncthreads();

#pragma unroll
        for (int kk = 0; kk < 8; kk++) {
            float4 a0 = *(const float4*)&xs[kk][ty * 8];
            float4 a1 = *(const float4*)&xs[kk][ty * 8 + 4];
            float4 b0 = *(const float4*)&ws[kk][tx * 8];
            float4 b1 = *(const float4*)&ws[kk][tx * 8 + 4];
            float ar[8] = {a0.x, a0.y, a0.z, a0.w, a1.x, a1.y, a1.z, a1.w};
            float br[8] = {b0.x, b0.y, b0.z, b0.w, b1.x, b1.y, b1.z, b1.w};
#pragma unroll
            for (int r = 0; r < 8; r++)
#pragma unroll
                for (int c = 0; c < 8; c++)
                    acc[r][c] += ar[r] * br[c];
        }
        __syncthreads();
    }

#pragma unroll
    for (int r = 0; r < 8; r++) {
        float4* dst = (float4*)&g_xw[(size_t)(m0 + ty * 8 + r) * HIDDEN + tx * 8];
        dst[0] = make_float4(acc[r][0], acc[r][1], acc[r][2], acc[r][3]);
        dst[1] = make_float4(acc[r][4], acc[r][5], acc[r][6], acc[r][7]);
    }
}

// ---------------------------------------------------------------------------
// K2: one CTA per batch, 512 threads (16 warps). Stages xw[b] (100KB) in smem:
//   h[j,:]  = relu((1+eps1)*xw[j,:] + sum_i adj[i,j]*xw[i,:] + b1)
//   out[b,:] = (1/N) * sum_j (h[j,:] @ W2) * ((1+eps2) + rowdeg[j]) + b2
// Warp w owns rows j = w + 16*r (r<13 for w<8, r<12 otherwise);
// lane owns 4 consecutive channels (float4).
// ---------------------------------------------------------------------------
#define CHUNK_I 40    // adjacency rows staged per step (200/40 = 5 steps)
#define PITCH_A 208   // padded row pitch; cols 200..207 are zero

__global__ __launch_bounds__(512, 1) void gin_fused_kernel(
    const int*   __restrict__ adj,
    const float* __restrict__ b1,
    const float* __restrict__ W2,
    const float* __restrict__ b2,
    const float* __restrict__ eps1p,
    const float* __restrict__ eps2p,
    float*       __restrict__ out)
{
    extern __shared__ float smem[];
    float* xw_s = smem;                           // 200*128 = 25600 f
    float* adjs = smem + N_NODE * HIDDEN;         // CHUNK_I*PITCH_A = 8320 f
    __shared__ float red[16][2];

    const int b    = blockIdx.x;
    const int t    = threadIdx.x;
    const int w    = t >> 5;                      // 0..15
    const int lane = t & 31;

    const float eps1 = *eps1p;
    const float eps2 = *eps2p;
    const int* adj_b = adj + (size_t)b * N_NODE * N_NODE;

    // Phase A: stage xw[b] into smem
    {
        const float4* src = (const float4*)&g_xw[(size_t)b * N_NODE * HIDDEN];
        float4* dst = (float4*)xw_s;
        for (int i = t; i < N_NODE * HIDDEN / 4; i += 512) dst[i] = src[i];
    }

    // Phase B: agg[j,f] = sum_i adj[i,j] * xw[i,f]
    float acc[13][4];
#pragma unroll
    for (int r = 0; r < 13; r++) {
        acc[r][0] = 0.f; acc[r][1] = 0.f; acc[r][2] = 0.f; acc[r][3] = 0.f;
    }

    for (int c0 = 0; c0 < N_NODE; c0 += CHUNK_I) {
        __syncthreads();
        // stage adjacency rows c0..c0+39 as float, zero-padded to PITCH_A
        for (int row = w; row < CHUNK_I; row += 16) {
            const int* src = &adj_b[(c0 + row) * N_NODE];
            float* dst = &adjs[row * PITCH_A];
            for (int col = lane; col < PITCH_A; col += 32)
                dst[col] = (col < N_NODE) ? (float)src[col] : 0.f;
        }
        __syncthreads();

#pragma unroll 2
        for (int ii = 0; ii < CHUNK_I; ii++) {
            const int i = c0 + ii;
            float4 xv = *(const float4*)&xw_s[i * HIDDEN + lane * 4];
            const float* arow = &adjs[ii * PITCH_A];
#pragma unroll
            for (int r = 0; r < 13; r++) {
                float a = arow[w + 16 * r];            // lane-uniform broadcast
                acc[r][0] += a * xv.x;
                acc[r][1] += a * xv.y;
                acc[r][2] += a * xv.z;
                acc[r][3] += a * xv.w;
            }
        }
    }

    // Phase C: epilogue — bias+relu, project by W2, rowdeg-weighted graph sum
    const float c1 = 1.f + eps1;
    const int rmax = (w < 8) ? 13 : 12;                // j = w + 16*r < 200
    float4 b1v = *(const float4*)&b1[lane * 4];
    float4 w2a = *(const float4*)&W2[(lane * 4) * 2];      // f0:{c0,c1} f0+1:{c0,c1}
    float4 w2b = *(const float4*)&W2[(lane * 4 + 2) * 2];  // f0+2,f0+3

    float sum0 = 0.f, sum1 = 0.f;
#pragma unroll 1
    for (int r = 0; r < rmax; r++) {
        const int j = w + 16 * r;
        float4 xj = *(const float4*)&xw_s[j * HIDDEN + lane * 4];
        float h0 = fmaxf(fmaf(c1, xj.x, acc[r][0]) + b1v.x, 0.f);
        float h1 = fmaxf(fmaf(c1, xj.y, acc[r][1]) + b1v.y, 0.f);
        float h2 = fmaxf(fmaf(c1, xj.z, acc[r][2]) + b1v.z, 0.f);
        float h3 = fmaxf(fmaf(c1, xj.w, acc[r][3]) + b1v.w, 0.f);
        float p0 = h0 * w2a.x + h1 * w2a.z + h2 * w2b.x + h3 * w2b.z;
        float p1 = h0 * w2a.y + h1 * w2a.w + h2 * w2b.y + h3 * w2b.w;
        // rowdeg[j] = sum of adjacency row j (coalesced, L2-hot)
        int d = 0;
        for (int q = lane; q < N_NODE; q += 32) d += adj_b[j * N_NODE + q];
#pragma unroll
        for (int off = 16; off; off >>= 1) {
            p0 += __shfl_xor_sync(0xffffffffu, p0, off);
            p1 += __shfl_xor_sync(0xffffffffu, p1, off);
            d  += __shfl_xor_sync(0xffffffffu, d,  off);
        }
        float wgt = (1.f + eps2) + (float)d;
        sum0 += p0 * wgt;
        sum1 += p1 * wgt;
    }

    if (lane == 0) { red[w][0] = sum0; red[w][1] = sum1; }
    __syncthreads();
    if (t == 0) {
        float s0 = 0.f, s1 = 0.f;
#pragma unroll
        for (int q = 0; q < 16; q++) { s0 += red[q][0]; s1 += red[q][1]; }
        out[b * 2 + 0] = s0 * (1.f / N_NODE) + b2[0];
        out[b * 2 + 1] = s1 * (1.f / N_NODE) + b2[1];
    }
}

// ---------------------------------------------------------------------------
extern "C" void kernel_launch(void* const* d_in, const int* in_sizes, int n_in,
                              void* d_out, int out_size)
{
    const float* x    = (const float*)d_in[0];   // [512,200,200]
    const int*   adj  = (const int*)  d_in[1];   // [512,200,200]
    const float* W1   = (const float*)d_in[2];   // [200,128]
    const float* b1   = (const float*)d_in[3];   // [128]
    const float* W2   = (const float*)d_in[4];   // [128,2]
    const float* b2   = (const float*)d_in[5];   // [2]
    const float* eps1 = (const float*)d_in[6];
    const float* eps2 = (const float*)d_in[7];
    float* out = (float*)d_out;                  // [512,2]

    const int smem2 = (N_NODE * HIDDEN + CHUNK_I * PITCH_A) * (int)sizeof(float); // 135680 B
    cudaFuncSetAttribute(gin_fused_kernel,
                         cudaFuncAttributeMaxDynamicSharedMemorySize, smem2);

    const int M = BATCH * N_NODE;                // 102400
    gemm_xw_kernel<<<M / 128, 256>>>(x, W1);
    gin_fused_kernel<<<BATCH, 512, smem2>>>(adj, b1, W2, b2, eps1, eps2, out);
}

// round 6
// speedup vs baseline: 1.1649x; 1.1649x over previous
#include <cuda_runtime.h>
#include <cuda_bf16.h>

#define BATCH  512
#define N_NODE 200
#define C_IN   200
#define HIDDEN 128

typedef unsigned long long ull;

// packed fp32 FMA: d = a*b + d  (sm_100+ f32x2, PTX-only)
#define FMA_F32X2(d, a, b) \
    asm("fma.rn.f32x2 %0, %1, %2, %0;" : "+l"(d) : "l"(a), "l"(b))

__device__ __forceinline__ ull pack2(float lo, float hi) {
    ull r;
    asm("mov.b64 %0, {%1, %2};" : "=l"(r)
        : "r"(__float_as_uint(lo)), "r"(__float_as_uint(hi)));
    return r;
}
__device__ __forceinline__ float2 unpk(ull v) {
    float2 r;
    r.x = __uint_as_float((unsigned)v);
    r.y = __uint_as_float((unsigned)(v >> 32));
    return r;
}

// scratch: xw = x @ W1, [BATCH, N_NODE, HIDDEN] fp32 (52.4 MB)
__device__ float g_xw[(size_t)BATCH * N_NODE * HIDDEN];

// ---------------------------------------------------------------------------
// K1: xw = x @ W1.  128x128 tile, 256 threads, 8x8 register tile via FFMA2
// (cols paired: ws float4 loads reinterpret directly as two f32x2 pairs).
// ---------------------------------------------------------------------------
__global__ __launch_bounds__(256) void gemm_xw_kernel(
    const float* __restrict__ x, const float* __restrict__ W1)
{
    __shared__ float xs[8][136];        // [kk][m], padded pitch
    __shared__ float ws[8][128];        // [kk][n]

    const int m0 = blockIdx.x * 128;
    const int t  = threadIdx.x;
    const int tx = t & 15;              // 16 col groups * 8 cols
    const int ty = t >> 4;              // 16 row groups * 8 rows

    const int xm = t >> 1;              // 0..127
    const int xk = (t & 1) * 4;         // 0 or 4
    const int wk = t >> 5;              // 0..7
    const int wn = (t & 31) * 4;        // 0..124

    ull acc2[8][4];                     // [row][col-pair]
#pragma unroll
    for (int r = 0; r < 8; r++)
#pragma unroll
        for (int c = 0; c < 4; c++) acc2[r][c] = 0ull;

    for (int k0 = 0; k0 < C_IN; k0 += 8) {
        float4 xv = *(const float4*)&x[(size_t)(m0 + xm) * C_IN + k0 + xk];
        xs[xk + 0][xm] = xv.x;
        xs[xk + 1][xm] = xv.y;
        xs[xk + 2][xm] = xv.z;
        xs[xk + 3][xm] = xv.w;
        *(float4*)&ws[wk][wn] = *(const float4*)&W1[(k0 + wk) * HIDDEN + wn];
        __syncthreads();

#pragma unroll
        for (int kk = 0; kk < 8; kk++) {
            float4 a0 = *(const float4*)&xs[kk][ty * 8];
            float4 a1 = *(const float4*)&xs[kk][ty * 8 + 4];
            ulonglong2 b0 = *(const ulonglong2*)&ws[kk][tx * 8];
            ulonglong2 b1 = *(const ulonglong2*)&ws[kk][tx * 8 + 4];
            ull bp[4] = {b0.x, b0.y, b1.x, b1.y};
            float ar[8] = {a0.x, a0.y, a0.z, a0.w, a1.x, a1.y, a1.z, a1.w};
#pragma unroll
            for (int r = 0; r < 8; r++) {
                ull as = pack2(ar[r], ar[r]);
#pragma unroll
                for (int c = 0; c < 4; c++)
                    FMA_F32X2(acc2[r][c], as, bp[c]);
            }
        }
        __syncthreads();
    }

#pragma unroll
    for (int r = 0; r < 8; r++) {
        float2 c0 = unpk(acc2[r][0]), c1 = unpk(acc2[r][1]);
        float2 c2 = unpk(acc2[r][2]), c3 = unpk(acc2[r][3]);
        float4* dst = (float4*)&g_xw[(size_t)(m0 + ty * 8 + r) * HIDDEN + tx * 8];
        dst[0] = make_float4(c0.x, c0.y, c1.x, c1.y);
        dst[1] = make_float4(c2.x, c2.y, c3.x, c3.y);
    }
}

// ---------------------------------------------------------------------------
// K2: one CTA per batch, 512 threads. xw[b] staged in smem.
// Phase B pairs ROWS for FFMA2: warp w owns rows j = 12w..12w+11
// (+ row 192+w for w<8). Adjacency pairs come free from 16B uniform loads;
// only the 4 xv channel-splats need packs. Row degrees computed during
// adjacency staging.
// ---------------------------------------------------------------------------
#define CHUNK_I 40    // adjacency rows staged per step (200/40 = 5 steps)
#define PITCH_A 208   // padded row pitch; cols 200..207 are zero

__global__ __launch_bounds__(512, 1) void gin_fused_kernel(
    const int*   __restrict__ adj,
    const float* __restrict__ b1,
    const float* __restrict__ W2,
    const float* __restrict__ b2,
    const float* __restrict__ eps1p,
    const float* __restrict__ eps2p,
    float*       __restrict__ out)
{
    extern __shared__ float smem[];
    float* xw_s = smem;                           // 25600 f
    float* adjs = smem + N_NODE * HIDDEN;         // 40*208 = 8320 f
    float* degs = adjs + CHUNK_I * PITCH_A;       // 200 f
    __shared__ float red[16][2];

    const int b    = blockIdx.x;
    const int t    = threadIdx.x;
    const int w    = t >> 5;                      // 0..15
    const int lane = t & 31;

    const float eps1 = *eps1p;
    const float eps2 = *eps2p;
    const int* adj_b = adj + (size_t)b * N_NODE * N_NODE;

    // Phase A: stage xw[b] into smem
    {
        const float4* src = (const float4*)&g_xw[(size_t)b * N_NODE * HIDDEN];
        float4* dst = (float4*)xw_s;
        for (int i = t; i < N_NODE * HIDDEN / 4; i += 512) dst[i] = src[i];
    }

    // Phase B accumulators: 6 row-pairs x 4 channels, plus extra row (w<8)
    ull acc2[6][4];
#pragma unroll
    for (int rp = 0; rp < 6; rp++)
#pragma unroll
        for (int c = 0; c < 4; c++) acc2[rp][c] = 0ull;
    float acce[4] = {0.f, 0.f, 0.f, 0.f};

    const int abase = 12 * w;                     // warp's a-vector base (16B aligned)

    for (int c0 = 0; c0 < N_NODE; c0 += CHUNK_I) {
        __syncthreads();
        // stage adjacency rows c0..c0+39 (zero-padded) + row-degree sums
        for (int row = w; row < CHUNK_I; row += 16) {
            const int* src = &adj_b[(c0 + row) * N_NODE];
            float* dst = &adjs[row * PITCH_A];
            float s = 0.f;
            for (int col = lane; col < PITCH_A; col += 32) {
                float v = (col < N_NODE) ? (float)src[col] : 0.f;
                dst[col] = v;
                s += v;
            }
#pragma unroll
            for (int off = 16; off; off >>= 1)
                s += __shfl_xor_sync(0xffffffffu, s, off);
            if (lane == 0) degs[c0 + row] = s;
        }
        __syncthreads();

#pragma unroll 2
        for (int ii = 0; ii < CHUNK_I; ii++) {
            const int i = c0 + ii;
            float4 xv = *(const float4*)&xw_s[i * HIDDEN + lane * 4];
            ull xs0 = pack2(xv.x, xv.x);
            ull xs1 = pack2(xv.y, xv.y);
            ull xs2 = pack2(xv.z, xv.z);
            ull xs3 = pack2(xv.w, xv.w);
            const float* arow = &adjs[ii * PITCH_A];
            // 12 a-values = 3 warp-uniform 16B loads -> 6 f32x2 pairs, no packs
            ulonglong2 av0 = *(const ulonglong2*)&arow[abase];
            ulonglong2 av1 = *(const ulonglong2*)&arow[abase + 4];
            ulonglong2 av2 = *(const ulonglong2*)&arow[abase + 8];
            ull ap[6] = {av0.x, av0.y, av1.x, av1.y, av2.x, av2.y};
#pragma unroll
            for (int rp = 0; rp < 6; rp++) {
                FMA_F32X2(acc2[rp][0], ap[rp], xs0);
                FMA_F32X2(acc2[rp][1], ap[rp], xs1);
                FMA_F32X2(acc2[rp][2], ap[rp], xs2);
                FMA_F32X2(acc2[rp][3], ap[rp], xs3);
            }
            if (w < 8) {                           // extra row j = 192 + w
                float ae = arow[192 + w];
                acce[0] += ae * xv.x;
                acce[1] += ae * xv.y;
                acce[2] += ae * xv.z;
                acce[3] += ae * xv.w;
            }
        }
    }

    // Phase C: epilogue
    const float c1 = 1.f + eps1;
    float4 b1v = *(const float4*)&b1[lane * 4];
    float4 w2a = *(const float4*)&W2[(lane * 4) * 2];      // f0,f0+1 x {c0,c1}
    float4 w2b = *(const float4*)&W2[(lane * 4 + 2) * 2];  // f0+2,f0+3

    float sum0 = 0.f, sum1 = 0.f;

#pragma unroll 1
    for (int r = 0; r < 13; r++) {
        float a0, a1, a2, a3;
        int j;
        if (r < 12) {
            j = 12 * w + r;
            int rp = r >> 1;
            float2 u0 = unpk(acc2[rp][0]);
            float2 u1 = unpk(acc2[rp][1]);
            float2 u2 = unpk(acc2[rp][2]);
            float2 u3 = unpk(acc2[rp][3]);
            if (r & 1) { a0 = u0.y; a1 = u1.y; a2 = u2.y; a3 = u3.y; }
            else       { a0 = u0.x; a1 = u1.x; a2 = u2.x; a3 = u3.x; }
        } else {
            if (w >= 8) break;
            j = 192 + w;
            a0 = acce[0]; a1 = acce[1]; a2 = acce[2]; a3 = acce[3];
        }
        float4 xj = *(const float4*)&xw_s[j * HIDDEN + lane * 4];
        float h0 = fmaxf(fmaf(c1, xj.x, a0) + b1v.x, 0.f);
        float h1 = fmaxf(fmaf(c1, xj.y, a1) + b1v.y, 0.f);
        float h2 = fmaxf(fmaf(c1, xj.z, a2) + b1v.z, 0.f);
        float h3 = fmaxf(fmaf(c1, xj.w, a3) + b1v.w, 0.f);
        float p0 = h0 * w2a.x + h1 * w2a.z + h2 * w2b.x + h3 * w2b.z;
        float p1 = h0 * w2a.y + h1 * w2a.w + h2 * w2b.y + h3 * w2b.w;
#pragma unroll
        for (int off = 16; off; off >>= 1) {
            p0 += __shfl_xor_sync(0xffffffffu, p0, off);
            p1 += __shfl_xor_sync(0xffffffffu, p1, off);
        }
        float wgt = (1.f + eps2) + degs[j];        // smem, precomputed
        sum0 += p0 * wgt;
        sum1 += p1 * wgt;
    }

    if (lane == 0) { red[w][0] = sum0; red[w][1] = sum1; }
    __syncthreads();
    if (t == 0) {
        float s0 = 0.f, s1 = 0.f;
#pragma unroll
        for (int q = 0; q < 16; q++) { s0 += red[q][0]; s1 += red[q][1]; }
        out[b * 2 + 0] = s0 * (1.f / N_NODE) + b2[0];
        out[b * 2 + 1] = s1 * (1.f / N_NODE) + b2[1];
    }
}

// ---------------------------------------------------------------------------
extern "C" void kernel_launch(void* const* d_in, const int* in_sizes, int n_in,
                              void* d_out, int out_size)
{
    const float* x    = (const float*)d_in[0];   // [512,200,200]
    const int*   adj  = (const int*)  d_in[1];   // [512,200,200]
    const float* W1   = (const float*)d_in[2];   // [200,128]
    const float* b1   = (const float*)d_in[3];   // [128]
    const float* W2   = (const float*)d_in[4];   // [128,2]
    const float* b2   = (const float*)d_in[5];   // [2]
    const float* eps1 = (const float*)d_in[6];
    const float* eps2 = (const float*)d_in[7];
    float* out = (float*)d_out;                  // [512,2]

    const int smem2 = (N_NODE * HIDDEN + CHUNK_I * PITCH_A + 256) * (int)sizeof(float);
    cudaFuncSetAttribute(gin_fused_kernel,
                         cudaFuncAttributeMaxDynamicSharedMemorySize, smem2);

    const int M = BATCH * N_NODE;                // 102400
    gemm_xw_kernel<<<M / 128, 256>>>(x, W1);
    gin_fused_kernel<<<BATCH, 512, smem2>>>(adj, b1, W2, b2, eps1, eps2, out);
}

// round 9
// speedup vs baseline: 2.3458x; 2.0138x over previous
#include <cuda_runtime.h>
#include <cuda_bf16.h>
#include <cstdint>

#define BATCH  512
#define N_NODE 200
#define C_IN   200
#define HIDDEN 128

typedef unsigned long long ull;

// ===================== PTX helpers =====================
__device__ __forceinline__ uint32_t smem_u32(const void* p) {
    uint32_t a;
    asm("{ .reg .u64 t; cvta.to.shared.u64 t, %1; cvt.u32.u64 %0, t; }"
        : "=r"(a) : "l"(p));
    return a;
}

#define LDSM_X4(r0, r1, r2, r3, addr) \
    asm volatile("ldmatrix.sync.aligned.m8n8.x4.shared.b16 {%0,%1,%2,%3}, [%4];" \
        : "=r"(r0), "=r"(r1), "=r"(r2), "=r"(r3) : "r"(addr))

#define LDSM_X4T(r0, r1, r2, r3, addr) \
    asm volatile("ldmatrix.sync.aligned.m8n8.x4.trans.shared.b16 {%0,%1,%2,%3}, [%4];" \
        : "=r"(r0), "=r"(r1), "=r"(r2), "=r"(r3) : "r"(addr))

#define MMA16816(c, a0, a1, a2, a3, b0, b1) \
    asm volatile("mma.sync.aligned.m16n8k16.row.col.f32.bf16.bf16.f32 " \
        "{%0,%1,%2,%3}, {%4,%5,%6,%7}, {%8,%9}, {%0,%1,%2,%3};" \
        : "+f"((c)[0]), "+f"((c)[1]), "+f"((c)[2]), "+f"((c)[3]) \
        : "r"(a0), "r"(a1), "r"(a2), "r"(a3), "r"(b0), "r"(b1))

// packed fp32 FMA for K1
#define FMA_F32X2(d, a, b) \
    asm("fma.rn.f32x2 %0, %1, %2, %0;" : "+l"(d) : "l"(a), "l"(b))
__device__ __forceinline__ ull pack2(float lo, float hi) {
    ull r;
    asm("mov.b64 %0, {%1, %2};" : "=l"(r)
        : "r"(__float_as_uint(lo)), "r"(__float_as_uint(hi)));
    return r;
}
__device__ __forceinline__ float2 unpk(ull v) {
    float2 r;
    r.x = __uint_as_float((unsigned)v);
    r.y = __uint_as_float((unsigned)(v >> 32));
    return r;
}

// scratch: xw = x @ W1, [BATCH, N_NODE, HIDDEN] fp32 (52.4 MB)
__device__ float g_xw[(size_t)BATCH * N_NODE * HIDDEN];

// ---------------------------------------------------------------------------
// K1: xw = x @ W1 (SIMT FFMA2, unchanged)
// ---------------------------------------------------------------------------
__global__ __launch_bounds__(256) void gemm_xw_kernel(
    const float* __restrict__ x, const float* __restrict__ W1)
{
    __shared__ float xs[8][136];
    __shared__ float ws[8][128];

    const int m0 = blockIdx.x * 128;
    const int t  = threadIdx.x;
    const int tx = t & 15;
    const int ty = t >> 4;
    const int xm = t >> 1;
    const int xk = (t & 1) * 4;
    const int wk = t >> 5;
    const int wn = (t & 31) * 4;

    ull acc2[8][4];
#pragma unroll
    for (int r = 0; r < 8; r++)
#pragma unroll
        for (int c = 0; c < 4; c++) acc2[r][c] = 0ull;

    for (int k0 = 0; k0 < C_IN; k0 += 8) {
        float4 xv = *(const float4*)&x[(size_t)(m0 + xm) * C_IN + k0 + xk];
        xs[xk + 0][xm] = xv.x;
        xs[xk + 1][xm] = xv.y;
        xs[xk + 2][xm] = xv.z;
        xs[xk + 3][xm] = xv.w;
        *(float4*)&ws[wk][wn] = *(const float4*)&W1[(k0 + wk) * HIDDEN + wn];
        __syncthreads();
#pragma unroll
        for (int kk = 0; kk < 8; kk++) {
            float4 a0 = *(const float4*)&xs[kk][ty * 8];
            float4 a1 = *(const float4*)&xs[kk][ty * 8 + 4];
            ulonglong2 b0 = *(const ulonglong2*)&ws[kk][tx * 8];
            ulonglong2 b1 = *(const ulonglong2*)&ws[kk][tx * 8 + 4];
            ull bp[4] = {b0.x, b0.y, b1.x, b1.y};
            float ar[8] = {a0.x, a0.y, a0.z, a0.w, a1.x, a1.y, a1.z, a1.w};
#pragma unroll
            for (int r = 0; r < 8; r++) {
                ull as = pack2(ar[r], ar[r]);
#pragma unroll
                for (int c = 0; c < 4; c++)
                    FMA_F32X2(acc2[r][c], as, bp[c]);
            }
        }
        __syncthreads();
    }
#pragma unroll
    for (int r = 0; r < 8; r++) {
        float2 c0 = unpk(acc2[r][0]), c1 = unpk(acc2[r][1]);
        float2 c2 = unpk(acc2[r][2]), c3 = unpk(acc2[r][3]);
        float4* dst = (float4*)&g_xw[(size_t)(m0 + ty * 8 + r) * HIDDEN + tx * 8];
        dst[0] = make_float4(c0.x, c0.y, c1.x, c1.y);
        dst[1] = make_float4(c2.x, c2.y, c3.x, c3.y);
    }
}

// ---------------------------------------------------------------------------
// K2: one CTA per batch, 512 threads, mma.sync m16n8k16 bf16 (split hi/lo B).
//   agg[j,f] = sum_i adjT[j,i] * xw[i,f]
//   A = adjT [M=208 pad][K=208 pad] bf16, row-major, pitch 216 bf16 (432B)
//   B = xw   [K=208 pad][N=128]     bf16 hi+lo, k-major, pitch 136 bf16 (272B)
//   13 MMA warps, one m16-tile each; 13 k-slabs; 16 n8-tiles per warp.
//   degs[i] = ROW sum of adj (sum over 2nd index) -- fixed in round 9.
// ---------------------------------------------------------------------------
#define PITCH_A_B   432                 // bytes per A row (216 bf16)
#define PITCH_B_B   272                 // bytes per B row (136 bf16)
#define OFF_A       0                   // 208 * 432  = 89856
#define OFF_BHI     89856               // 208 * 272  = 56576
#define OFF_BLO     146432              // 56576
#define OFF_DEG     203008              // 208 floats = 832
#define OFF_PART    203840              // 208 * 2 floats = 1664
#define OFF_W2S     205504              // 256 floats = 1024
#define OFF_B1S     206528              // 128 floats = 512
#define SMEM_TOTAL  207040

__global__ __launch_bounds__(512, 1) void gin_fused_kernel(
    const int*   __restrict__ adj,
    const float* __restrict__ b1,
    const float* __restrict__ W2,
    const float* __restrict__ b2,
    const float* __restrict__ eps1p,
    const float* __restrict__ eps2p,
    float*       __restrict__ out)
{
    extern __shared__ char smem[];
    const uint32_t sbase = smem_u32(smem);
    float* degs = (float*)(smem + OFF_DEG);
    float* part = (float*)(smem + OFF_PART);
    float* w2s  = (float*)(smem + OFF_W2S);
    float* b1s  = (float*)(smem + OFF_B1S);

    const int b    = blockIdx.x;
    const int t    = threadIdx.x;
    const int w    = t >> 5;
    const int lane = t & 31;
    const int* adj_b = adj + (size_t)b * N_NODE * N_NODE;

    // ---- zero A, Bhi, Blo (pad regions must be 0, not garbage/NaN) ----
    {
        uint4* z = (uint4*)smem;                       // A..Blo = 203008 B
        for (int i = t; i < 203008 / 16; i += 512)
            z[i] = make_uint4(0u, 0u, 0u, 0u);
        if (t < 128) b1s[t] = b1[t];
        if (t < 256) w2s[t] = W2[t];
    }
    __syncthreads();

    // ---- stage B: xw[b] -> bf16 hi/lo, k-major [i][f] (no transpose) ----
    for (int idx = t; idx < 200 * 32; idx += 512) {
        const int i = idx >> 5;
        const int f = (idx & 31) * 4;
        float4 v = *(const float4*)&g_xw[((size_t)b * N_NODE + i) * HIDDEN + f];
        __nv_bfloat16 h0 = __float2bfloat16(v.x);
        __nv_bfloat16 h1 = __float2bfloat16(v.y);
        __nv_bfloat16 h2 = __float2bfloat16(v.z);
        __nv_bfloat16 h3 = __float2bfloat16(v.w);
        __nv_bfloat16 l0 = __float2bfloat16(v.x - __bfloat162float(h0));
        __nv_bfloat16 l1 = __float2bfloat16(v.y - __bfloat162float(h1));
        __nv_bfloat16 l2 = __float2bfloat16(v.z - __bfloat162float(h2));
        __nv_bfloat16 l3 = __float2bfloat16(v.w - __bfloat162float(h3));
        uint2 hp, lp;
        hp.x = (uint32_t)__bfloat16_as_ushort(h0) | ((uint32_t)__bfloat16_as_ushort(h1) << 16);
        hp.y = (uint32_t)__bfloat16_as_ushort(h2) | ((uint32_t)__bfloat16_as_ushort(h3) << 16);
        lp.x = (uint32_t)__bfloat16_as_ushort(l0) | ((uint32_t)__bfloat16_as_ushort(l1) << 16);
        lp.y = (uint32_t)__bfloat16_as_ushort(l2) | ((uint32_t)__bfloat16_as_ushort(l3) << 16);
        *(uint2*)(smem + OFF_BHI + i * PITCH_B_B + f * 2) = hp;
        *(uint2*)(smem + OFF_BLO + i * PITCH_B_B + f * 2) = lp;
    }

    // ---- stage A: adjT[j][i] = adj[i][j] (transpose) + ROW degrees ----
    // degs[i] = sum_k adj[i][k]  (row sum; this is the layer-2 weight)
    {
        for (int i = w; i < N_NODE; i += 16) {
            const int* row = &adj_b[i * N_NODE];
            int rsum = 0;
#pragma unroll
            for (int c = 0; c < 7; c++) {
                const int j = lane + 32 * c;
                if (j < N_NODE) {
                    int v = row[j];
                    *(unsigned short*)(smem + OFF_A + j * PITCH_A_B + i * 2) =
                        v ? (unsigned short)0x3F80u : (unsigned short)0u;
                    rsum += v;
                }
            }
#pragma unroll
            for (int off = 16; off; off >>= 1)
                rsum += __shfl_xor_sync(0xffffffffu, rsum, off);
            if (lane == 0) degs[i] = (float)rsum;
        }
    }
    __syncthreads();

    // ---- MMA + epilogue (warps 0..12; warp w owns rows 16w..16w+15) ----
    if (w < 13) {
        float acc[16][4];
#pragma unroll
        for (int n = 0; n < 16; n++) {
            acc[n][0] = 0.f; acc[n][1] = 0.f; acc[n][2] = 0.f; acc[n][3] = 0.f;
        }

        // ldmatrix lane address bases
        const uint32_t a_base = sbase + OFF_A
            + (uint32_t)(16 * w + (lane & 15)) * PITCH_A_B + (uint32_t)(lane >> 4) * 16;
        const uint32_t b_off = (uint32_t)(lane & 15) * PITCH_B_B + (uint32_t)(lane >> 4) * 16;
        const uint32_t bhi_base = sbase + OFF_BHI + b_off;
        const uint32_t blo_base = sbase + OFF_BLO + b_off;

#pragma unroll 1
        for (int ks = 0; ks < 13; ks++) {
            uint32_t a0, a1, a2, a3;
            LDSM_X4(a0, a1, a2, a3, a_base + (uint32_t)ks * 32);
            const uint32_t brow = (uint32_t)ks * 16 * PITCH_B_B;
#pragma unroll
            for (int nb = 0; nb < 8; nb++) {
                uint32_t h0, h1, h2, h3, l0, l1, l2, l3;
                LDSM_X4T(h0, h1, h2, h3, bhi_base + brow + (uint32_t)nb * 32);
                MMA16816(acc[2 * nb],     a0, a1, a2, a3, h0, h1);
                MMA16816(acc[2 * nb + 1], a0, a1, a2, a3, h2, h3);
                LDSM_X4T(l0, l1, l2, l3, blo_base + brow + (uint32_t)nb * 32);
                MMA16816(acc[2 * nb],     a0, a1, a2, a3, l0, l1);
                MMA16816(acc[2 * nb + 1], a0, a1, a2, a3, l2, l3);
            }
        }

        // epilogue: h = relu((1+eps1)*xw + agg + b1); project W2; weight; stash
        const float c1x = 1.f + *eps1p;
        const float c2x = 1.f + *eps2p;
        const int g  = lane >> 2;
        const int tg = lane & 3;
        const int ja = 16 * w + g;
        const int jb = ja + 8;

        float pa0 = 0.f, pa1 = 0.f, pb0 = 0.f, pb1 = 0.f;
#pragma unroll
        for (int nt = 0; nt < 16; nt++) {
            const int f0 = nt * 8 + tg * 2;
            uint32_t ha = *(uint32_t*)(smem + OFF_BHI + ja * PITCH_B_B + f0 * 2);
            uint32_t la = *(uint32_t*)(smem + OFF_BLO + ja * PITCH_B_B + f0 * 2);
            uint32_t hb = *(uint32_t*)(smem + OFF_BHI + jb * PITCH_B_B + f0 * 2);
            uint32_t lb = *(uint32_t*)(smem + OFF_BLO + jb * PITCH_B_B + f0 * 2);
            float xa0 = __uint_as_float(ha << 16) + __uint_as_float(la << 16);
            float xa1 = __uint_as_float(ha & 0xFFFF0000u) + __uint_as_float(la & 0xFFFF0000u);
            float xb0 = __uint_as_float(hb << 16) + __uint_as_float(lb << 16);
            float xb1 = __uint_as_float(hb & 0xFFFF0000u) + __uint_as_float(lb & 0xFFFF0000u);
            float bv0 = b1s[f0], bv1 = b1s[f0 + 1];
            float w00 = w2s[f0 * 2],       w01 = w2s[f0 * 2 + 1];
            float w10 = w2s[(f0 + 1) * 2], w11 = w2s[(f0 + 1) * 2 + 1];

            float ha0 = fmaxf(fmaf(c1x, xa0, acc[nt][0]) + bv0, 0.f);
            float ha1 = fmaxf(fmaf(c1x, xa1, acc[nt][1]) + bv1, 0.f);
            float hb0 = fmaxf(fmaf(c1x, xb0, acc[nt][2]) + bv0, 0.f);
            float hb1 = fmaxf(fmaf(c1x, xb1, acc[nt][3]) + bv1, 0.f);

            pa0 += ha0 * w00 + ha1 * w10;
            pa1 += ha0 * w01 + ha1 * w11;
            pb0 += hb0 * w00 + hb1 * w10;
            pb1 += hb0 * w01 + hb1 * w11;
        }
        // reduce across the 4 threads of each row group
#pragma unroll
        for (int off = 1; off <= 2; off <<= 1) {
            pa0 += __shfl_xor_sync(0xffffffffu, pa0, off);
            pa1 += __shfl_xor_sync(0xffffffffu, pa1, off);
            pb0 += __shfl_xor_sync(0xffffffffu, pb0, off);
            pb1 += __shfl_xor_sync(0xffffffffu, pb1, off);
        }
        if (tg == 0) {
            float wa = (ja < N_NODE) ? (c2x + degs[ja]) : 0.f;
            float wb = (jb < N_NODE) ? (c2x + degs[jb]) : 0.f;
            part[ja * 2 + 0] = (ja < N_NODE) ? pa0 * wa : 0.f;
            part[ja * 2 + 1] = (ja < N_NODE) ? pa1 * wa : 0.f;
            part[jb * 2 + 0] = (jb < N_NODE) ? pb0 * wb : 0.f;
            part[jb * 2 + 1] = (jb < N_NODE) ? pb1 * wb : 0.f;
        }
    }
    __syncthreads();

    // ---- final graph reduction ----
    if (w == 0) {
        float s0 = 0.f, s1 = 0.f;
#pragma unroll
        for (int c = 0; c < 7; c++) {
            const int idx = lane + 32 * c;
            if (idx < 208) { s0 += part[idx * 2 + 0]; s1 += part[idx * 2 + 1]; }
        }
#pragma unroll
        for (int off = 16; off; off >>= 1) {
            s0 += __shfl_xor_sync(0xffffffffu, s0, off);
            s1 += __shfl_xor_sync(0xffffffffu, s1, off);
        }
        if (lane == 0) {
            out[b * 2 + 0] = s0 * (1.f / N_NODE) + b2[0];
            out[b * 2 + 1] = s1 * (1.f / N_NODE) + b2[1];
        }
    }
}

// ---------------------------------------------------------------------------
extern "C" void kernel_launch(void* const* d_in, const int* in_sizes, int n_in,
                              void* d_out, int out_size)
{
    const float* x    = (const float*)d_in[0];   // [512,200,200]
    const int*   adj  = (const int*)  d_in[1];   // [512,200,200]
    const float* W1   = (const float*)d_in[2];   // [200,128]
    const float* b1   = (const float*)d_in[3];   // [128]
    const float* W2   = (const float*)d_in[4];   // [128,2]
    const float* b2   = (const float*)d_in[5];   // [2]
    const float* eps1 = (const float*)d_in[6];
    const float* eps2 = (const float*)d_in[7];
    float* out = (float*)d_out;                  // [512,2]

    cudaFuncSetAttribute(gin_fused_kernel,
                         cudaFuncAttributeMaxDynamicSharedMemorySize, SMEM_TOTAL);

    const int M = BATCH * N_NODE;                // 102400
    gemm_xw_kernel<<<M / 128, 256>>>(x, W1);
    gin_fused_kernel<<<BATCH, 512, SMEM_TOTAL>>>(adj, b1, W2, b2, eps1, eps2, out);
}

// round 10
// speedup vs baseline: 2.7334x; 1.1652x over previous
#include <cuda_runtime.h>
#include <cuda_bf16.h>
#include <cstdint>

#define BATCH  512
#define N_NODE 200
#define C_IN   200
#define HIDDEN 128

typedef unsigned long long ull;

// ===================== PTX helpers =====================
__device__ __forceinline__ uint32_t smem_u32(const void* p) {
    uint32_t a;
    asm("{ .reg .u64 t; cvta.to.shared.u64 t, %1; cvt.u32.u64 %0, t; }"
        : "=r"(a) : "l"(p));
    return a;
}

#define LDSM_X4(r0, r1, r2, r3, addr) \
    asm volatile("ldmatrix.sync.aligned.m8n8.x4.shared.b16 {%0,%1,%2,%3}, [%4];" \
        : "=r"(r0), "=r"(r1), "=r"(r2), "=r"(r3) : "r"(addr))

#define LDSM_X4T(r0, r1, r2, r3, addr) \
    asm volatile("ldmatrix.sync.aligned.m8n8.x4.trans.shared.b16 {%0,%1,%2,%3}, [%4];" \
        : "=r"(r0), "=r"(r1), "=r"(r2), "=r"(r3) : "r"(addr))

#define MMA16816(c, a0, a1, a2, a3, b0, b1) \
    asm volatile("mma.sync.aligned.m16n8k16.row.col.f32.bf16.bf16.f32 " \
        "{%0,%1,%2,%3}, {%4,%5,%6,%7}, {%8,%9}, {%0,%1,%2,%3};" \
        : "+f"((c)[0]), "+f"((c)[1]), "+f"((c)[2]), "+f"((c)[3]) \
        : "r"(a0), "r"(a1), "r"(a2), "r"(a3), "r"(b0), "r"(b1))

// scratch: xw = x @ W1, [BATCH, N_NODE, HIDDEN] fp32 (52.4 MB)
__device__ float g_xw[(size_t)BATCH * N_NODE * HIDDEN];
// W1 pre-split into bf16 hi/lo, zero-padded to K=208 rows: [208][128]
__device__ __nv_bfloat16 g_w1hi[208 * HIDDEN];
__device__ __nv_bfloat16 g_w1lo[208 * HIDDEN];

// ---------------------------------------------------------------------------
// K0: split W1 fp32 -> bf16 hi/lo with zero k-padding (runs once, tiny)
// ---------------------------------------------------------------------------
__global__ void split_w1_kernel(const float* __restrict__ W1)
{
    int idx = blockIdx.x * 256 + threadIdx.x;          // 0 .. 208*128-1
    if (idx >= 208 * HIDDEN) return;
    int k = idx / HIDDEN;
    float v = (k < C_IN) ? W1[idx] : 0.f;
    __nv_bfloat16 h = __float2bfloat16(v);
    __nv_bfloat16 l = __float2bfloat16(v - __bfloat162float(h));
    g_w1hi[idx] = h;
    g_w1lo[idx] = l;
}

// ---------------------------------------------------------------------------
// K1: xw = x @ W1 via mma.sync split-bf16 (3 products: hh + hl + lh).
//   Per CTA: M-tile 128 (8 warps x m16), N=128, K=208 (13 k16 slabs).
//   A = x tile hi/lo, row-major, pitch 432B. B = W1 hi/lo, k-major, pitch 272B.
// ---------------------------------------------------------------------------
#define K1_PA     432
#define K1_PB     272
#define K1_AHI    0                    // 128*432 = 55296
#define K1_ALO    55296
#define K1_BHI    110592               // 208*272 = 56576
#define K1_BLO    167168
#define K1_SMEM   223744

__global__ __launch_bounds__(256, 1) void gemm_xw_mma_kernel(
    const float* __restrict__ x)
{
    extern __shared__ char smem[];
    const uint32_t sbase = smem_u32(smem);

    const int m0   = blockIdx.x * 128;
    const int t    = threadIdx.x;
    const int w    = t >> 5;
    const int lane = t & 31;

    // ---- stage A: x tile [128 x 200] fp32 -> hi/lo bf16, pitch 432 ----
    for (int idx = t; idx < 128 * 50; idx += 256) {    // 50 float4 per row
        const int m = idx / 50;
        const int q = idx % 50;                        // k = 4q
        float4 v = *(const float4*)&x[(size_t)(m0 + m) * C_IN + q * 4];
        __nv_bfloat16 h0 = __float2bfloat16(v.x);
        __nv_bfloat16 h1 = __float2bfloat16(v.y);
        __nv_bfloat16 h2 = __float2bfloat16(v.z);
        __nv_bfloat16 h3 = __float2bfloat16(v.w);
        __nv_bfloat16 l0 = __float2bfloat16(v.x - __bfloat162float(h0));
        __nv_bfloat16 l1 = __float2bfloat16(v.y - __bfloat162float(h1));
        __nv_bfloat16 l2 = __float2bfloat16(v.z - __bfloat162float(h2));
        __nv_bfloat16 l3 = __float2bfloat16(v.w - __bfloat162float(h3));
        uint2 hp, lp;
        hp.x = (uint32_t)__bfloat16_as_ushort(h0) | ((uint32_t)__bfloat16_as_ushort(h1) << 16);
        hp.y = (uint32_t)__bfloat16_as_ushort(h2) | ((uint32_t)__bfloat16_as_ushort(h3) << 16);
        lp.x = (uint32_t)__bfloat16_as_ushort(l0) | ((uint32_t)__bfloat16_as_ushort(l1) << 16);
        lp.y = (uint32_t)__bfloat16_as_ushort(l2) | ((uint32_t)__bfloat16_as_ushort(l3) << 16);
        *(uint2*)(smem + K1_AHI + m * K1_PA + q * 8) = hp;
        *(uint2*)(smem + K1_ALO + m * K1_PA + q * 8) = lp;
    }
    // zero A k-pad (k = 200..207, 16B per row)
    if (t < 128) {
        *(uint4*)(smem + K1_AHI + t * K1_PA + 400) = make_uint4(0u, 0u, 0u, 0u);
        *(uint4*)(smem + K1_ALO + t * K1_PA + 400) = make_uint4(0u, 0u, 0u, 0u);
    }

    // ---- stage B: copy pre-split W1 hi/lo (gmem pitch 256B -> smem 272B) ----
    for (int idx = t; idx < 208 * 16; idx += 256) {    // 16 uint4 per row
        const int r = idx >> 4;
        const int c = idx & 15;
        *(uint4*)(smem + K1_BHI + r * K1_PB + c * 16) =
            ((const uint4*)g_w1hi)[r * 16 + c];
        *(uint4*)(smem + K1_BLO + r * K1_PB + c * 16) =
            ((const uint4*)g_w1lo)[r * 16 + c];
    }
    __syncthreads();

    // ---- MMA: warp w owns rows 16w..16w+15, all 128 n ----
    float acc[16][4];
#pragma unroll
    for (int n = 0; n < 16; n++) {
        acc[n][0] = 0.f; acc[n][1] = 0.f; acc[n][2] = 0.f; acc[n][3] = 0.f;
    }

    const uint32_t ah_base = sbase + K1_AHI
        + (uint32_t)(16 * w + (lane & 15)) * K1_PA + (uint32_t)(lane >> 4) * 16;
    const uint32_t al_base = ah_base + (K1_ALO - K1_AHI);
    const uint32_t b_off   = (uint32_t)(lane & 15) * K1_PB + (uint32_t)(lane >> 4) * 16;
    const uint32_t bhi_base = sbase + K1_BHI + b_off;
    const uint32_t blo_base = sbase + K1_BLO + b_off;

#pragma unroll 1
    for (int ks = 0; ks < 13; ks++) {
        uint32_t ah0, ah1, ah2, ah3, al0, al1, al2, al3;
        LDSM_X4(ah0, ah1, ah2, ah3, ah_base + (uint32_t)ks * 32);
        LDSM_X4(al0, al1, al2, al3, al_base + (uint32_t)ks * 32);
        const uint32_t brow = (uint32_t)ks * 16 * K1_PB;
#pragma unroll
        for (int nb = 0; nb < 8; nb++) {
            uint32_t h0, h1, h2, h3, l0, l1, l2, l3;
            LDSM_X4T(h0, h1, h2, h3, bhi_base + brow + (uint32_t)nb * 32);
            MMA16816(acc[2 * nb],     ah0, ah1, ah2, ah3, h0, h1);   // xh*wh
            MMA16816(acc[2 * nb + 1], ah0, ah1, ah2, ah3, h2, h3);
            MMA16816(acc[2 * nb],     al0, al1, al2, al3, h0, h1);   // xl*wh
            MMA16816(acc[2 * nb + 1], al0, al1, al2, al3, h2, h3);
            LDSM_X4T(l0, l1, l2, l3, blo_base + brow + (uint32_t)nb * 32);
            MMA16816(acc[2 * nb],     ah0, ah1, ah2, ah3, l0, l1);   // xh*wl
            MMA16816(acc[2 * nb + 1], ah0, ah1, ah2, ah3, l2, l3);
        }
    }

    // ---- epilogue: write fragments to g_xw ----
    const int g  = lane >> 2;
    const int tg = lane & 3;
    const size_t ra = (size_t)(m0 + 16 * w + g) * HIDDEN;
    const size_t rb = ra + 8 * HIDDEN;
#pragma unroll
    for (int nt = 0; nt < 16; nt++) {
        const int f = nt * 8 + tg * 2;
        *(float2*)&g_xw[ra + f] = make_float2(acc[nt][0], acc[nt][1]);
        *(float2*)&g_xw[rb + f] = make_float2(acc[nt][2], acc[nt][3]);
    }
}

// ---------------------------------------------------------------------------
// K2: one CTA per batch, 512 threads, mma.sync m16n8k16 bf16 (split hi/lo B).
// (unchanged from round 9 — passing at rel_err 1.9e-6)
// ---------------------------------------------------------------------------
#define PITCH_A_B   432
#define PITCH_B_B   272
#define OFF_A       0
#define OFF_BHI     89856
#define OFF_BLO     146432
#define OFF_DEG     203008
#define OFF_PART    203840
#define OFF_W2S     205504
#define OFF_B1S     206528
#define SMEM_TOTAL  207040

__global__ __launch_bounds__(512, 1) void gin_fused_kernel(
    const int*   __restrict__ adj,
    const float* __restrict__ b1,
    const float* __restrict__ W2,
    const float* __restrict__ b2,
    const float* __restrict__ eps1p,
    const float* __restrict__ eps2p,
    float*       __restrict__ out)
{
    extern __shared__ char smem[];
    const uint32_t sbase = smem_u32(smem);
    float* degs = (float*)(smem + OFF_DEG);
    float* part = (float*)(smem + OFF_PART);
    float* w2s  = (float*)(smem + OFF_W2S);
    float* b1s  = (float*)(smem + OFF_B1S);

    const int b    = blockIdx.x;
    const int t    = threadIdx.x;
    const int w    = t >> 5;
    const int lane = t & 31;
    const int* adj_b = adj + (size_t)b * N_NODE * N_NODE;

    {
        uint4* z = (uint4*)smem;
        for (int i = t; i < 203008 / 16; i += 512)
            z[i] = make_uint4(0u, 0u, 0u, 0u);
        if (t < 128) b1s[t] = b1[t];
        if (t < 256) w2s[t] = W2[t];
    }
    __syncthreads();

    for (int idx = t; idx < 200 * 32; idx += 512) {
        const int i = idx >> 5;
        const int f = (idx & 31) * 4;
        float4 v = *(const float4*)&g_xw[((size_t)b * N_NODE + i) * HIDDEN + f];
        __nv_bfloat16 h0 = __float2bfloat16(v.x);
        __nv_bfloat16 h1 = __float2bfloat16(v.y);
        __nv_bfloat16 h2 = __float2bfloat16(v.z);
        __nv_bfloat16 h3 = __float2bfloat16(v.w);
        __nv_bfloat16 l0 = __float2bfloat16(v.x - __bfloat162float(h0));
        __nv_bfloat16 l1 = __float2bfloat16(v.y - __bfloat162float(h1));
        __nv_bfloat16 l2 = __float2bfloat16(v.z - __bfloat162float(h2));
        __nv_bfloat16 l3 = __float2bfloat16(v.w - __bfloat162float(h3));
        uint2 hp, lp;
        hp.x = (uint32_t)__bfloat16_as_ushort(h0) | ((uint32_t)__bfloat16_as_ushort(h1) << 16);
        hp.y = (uint32_t)__bfloat16_as_ushort(h2) | ((uint32_t)__bfloat16_as_ushort(h3) << 16);
        lp.x = (uint32_t)__bfloat16_as_ushort(l0) | ((uint32_t)__bfloat16_as_ushort(l1) << 16);
        lp.y = (uint32_t)__bfloat16_as_ushort(l2) | ((uint32_t)__bfloat16_as_ushort(l3) << 16);
        *(uint2*)(smem + OFF_BHI + i * PITCH_B_B + f * 2) = hp;
        *(uint2*)(smem + OFF_BLO + i * PITCH_B_B + f * 2) = lp;
    }

    {
        for (int i = w; i < N_NODE; i += 16) {
            const int* row = &adj_b[i * N_NODE];
            int rsum = 0;
#pragma unroll
            for (int c = 0; c < 7; c++) {
                const int j = lane + 32 * c;
                if (j < N_NODE) {
                    int v = row[j];
                    *(unsigned short*)(smem + OFF_A + j * PITCH_A_B + i * 2) =
                        v ? (unsigned short)0x3F80u : (unsigned short)0u;
                    rsum += v;
                }
            }
#pragma unroll
            for (int off = 16; off; off >>= 1)
                rsum += __shfl_xor_sync(0xffffffffu, rsum, off);
            if (lane == 0) degs[i] = (float)rsum;
        }
    }
    __syncthreads();

    if (w < 13) {
        float acc[16][4];
#pragma unroll
        for (int n = 0; n < 16; n++) {
            acc[n][0] = 0.f; acc[n][1] = 0.f; acc[n][2] = 0.f; acc[n][3] = 0.f;
        }

        const uint32_t a_base = sbase + OFF_A
            + (uint32_t)(16 * w + (lane & 15)) * PITCH_A_B + (uint32_t)(lane >> 4) * 16;
        const uint32_t b_off = (uint32_t)(lane & 15) * PITCH_B_B + (uint32_t)(lane >> 4) * 16;
        const uint32_t bhi_base = sbase + OFF_BHI + b_off;
        const uint32_t blo_base = sbase + OFF_BLO + b_off;

#pragma unroll 1
        for (int ks = 0; ks < 13; ks++) {
            uint32_t a0, a1, a2, a3;
            LDSM_X4(a0, a1, a2, a3, a_base + (uint32_t)ks * 32);
            const uint32_t brow = (uint32_t)ks * 16 * PITCH_B_B;
#pragma unroll
            for (int nb = 0; nb < 8; nb++) {
                uint32_t h0, h1, h2, h3, l0, l1, l2, l3;
                LDSM_X4T(h0, h1, h2, h3, bhi_base + brow + (uint32_t)nb * 32);
                MMA16816(acc[2 * nb],     a0, a1, a2, a3, h0, h1);
                MMA16816(acc[2 * nb + 1], a0, a1, a2, a3, h2, h3);
                LDSM_X4T(l0, l1, l2, l3, blo_base + brow + (uint32_t)nb * 32);
                MMA16816(acc[2 * nb],     a0, a1, a2, a3, l0, l1);
                MMA16816(acc[2 * nb + 1], a0, a1, a2, a3, l2, l3);
            }
        }

        const float c1x = 1.f + *eps1p;
        const float c2x = 1.f + *eps2p;
        const int g  = lane >> 2;
        const int tg = lane & 3;
        const int ja = 16 * w + g;
        const int jb = ja + 8;

        float pa0 = 0.f, pa1 = 0.f, pb0 = 0.f, pb1 = 0.f;
#pragma unroll
        for (int nt = 0; nt < 16; nt++) {
            const int f0 = nt * 8 + tg * 2;
            uint32_t ha = *(uint32_t*)(smem + OFF_BHI + ja * PITCH_B_B + f0 * 2);
            uint32_t la = *(uint32_t*)(smem + OFF_BLO + ja * PITCH_B_B + f0 * 2);
            uint32_t hb = *(uint32_t*)(smem + OFF_BHI + jb * PITCH_B_B + f0 * 2);
            uint32_t lb = *(uint32_t*)(smem + OFF_BLO + jb * PITCH_B_B + f0 * 2);
            float xa0 = __uint_as_float(ha << 16) + __uint_as_float(la << 16);
            float xa1 = __uint_as_float(ha & 0xFFFF0000u) + __uint_as_float(la & 0xFFFF0000u);
            float xb0 = __uint_as_float(hb << 16) + __uint_as_float(lb << 16);
            float xb1 = __uint_as_float(hb & 0xFFFF0000u) + __uint_as_float(lb & 0xFFFF0000u);
            float bv0 = b1s[f0], bv1 = b1s[f0 + 1];
            float w00 = w2s[f0 * 2],       w01 = w2s[f0 * 2 + 1];
            float w10 = w2s[(f0 + 1) * 2], w11 = w2s[(f0 + 1) * 2 + 1];

            float ha0 = fmaxf(fmaf(c1x, xa0, acc[nt][0]) + bv0, 0.f);
            float ha1 = fmaxf(fmaf(c1x, xa1, acc[nt][1]) + bv1, 0.f);
            float hb0 = fmaxf(fmaf(c1x, xb0, acc[nt][2]) + bv0, 0.f);
            float hb1 = fmaxf(fmaf(c1x, xb1, acc[nt][3]) + bv1, 0.f);

            pa0 += ha0 * w00 + ha1 * w10;
            pa1 += ha0 * w01 + ha1 * w11;
            pb0 += hb0 * w00 + hb1 * w10;
            pb1 += hb0 * w01 + hb1 * w11;
        }
#pragma unroll
        for (int off = 1; off <= 2; off <<= 1) {
            pa0 += __shfl_xor_sync(0xffffffffu, pa0, off);
            pa1 += __shfl_xor_sync(0xffffffffu, pa1, off);
            pb0 += __shfl_xor_sync(0xffffffffu, pb0, off);
            pb1 += __shfl_xor_sync(0xffffffffu, pb1, off);
        }
        if (tg == 0) {
            float wa = (ja < N_NODE) ? (c2x + degs[ja]) : 0.f;
            float wb = (jb < N_NODE) ? (c2x + degs[jb]) : 0.f;
            part[ja * 2 + 0] = (ja < N_NODE) ? pa0 * wa : 0.f;
            part[ja * 2 + 1] = (ja < N_NODE) ? pa1 * wa : 0.f;
            part[jb * 2 + 0] = (jb < N_NODE) ? pb0 * wb : 0.f;
            part[jb * 2 + 1] = (jb < N_NODE) ? pb1 * wb : 0.f;
        }
    }
    __syncthreads();

    if (w == 0) {
        float s0 = 0.f, s1 = 0.f;
#pragma unroll
        for (int c = 0; c < 7; c++) {
            const int idx = lane + 32 * c;
            if (idx < 208) { s0 += part[idx * 2 + 0]; s1 += part[idx * 2 + 1]; }
        }
#pragma unroll
        for (int off = 16; off; off >>= 1) {
            s0 += __shfl_xor_sync(0xffffffffu, s0, off);
            s1 += __shfl_xor_sync(0xffffffffu, s1, off);
        }
        if (lane == 0) {
            out[b * 2 + 0] = s0 * (1.f / N_NODE) + b2[0];
            out[b * 2 + 1] = s1 * (1.f / N_NODE) + b2[1];
        }
    }
}

// ---------------------------------------------------------------------------
extern "C" void kernel_launch(void* const* d_in, const int* in_sizes, int n_in,
                              void* d_out, int out_size)
{
    const float* x    = (const float*)d_in[0];   // [512,200,200]
    const int*   adj  = (const int*)  d_in[1];   // [512,200,200]
    const float* W1   = (const float*)d_in[2];   // [200,128]
    const float* b1   = (const float*)d_in[3];   // [128]
    const float* W2   = (const float*)d_in[4];   // [128,2]
    const float* b2   = (const float*)d_in[5];   // [2]
    const float* eps1 = (const float*)d_in[6];
    const float* eps2 = (const float*)d_in[7];
    float* out = (float*)d_out;                  // [512,2]

    cudaFuncSetAttribute(gemm_xw_mma_kernel,
                         cudaFuncAttributeMaxDynamicSharedMemorySize, K1_SMEM);
    cudaFuncSetAttribute(gin_fused_kernel,
                         cudaFuncAttributeMaxDynamicSharedMemorySize, SMEM_TOTAL);

    split_w1_kernel<<<(208 * HIDDEN + 255) / 256, 256>>>(W1);
    gemm_xw_mma_kernel<<<BATCH * N_NODE / 128, 256, K1_SMEM>>>(x);
    gin_fused_kernel<<<BATCH, 512, SMEM_TOTAL>>>(adj, b1, W2, b2, eps1, eps2, out);
}

// round 11
// speedup vs baseline: 2.9494x; 1.0790x over previous
#include <cuda_runtime.h>
#include <cuda_bf16.h>
#include <cstdint>

#define BATCH  512
#define N_NODE 200
#define C_IN   200
#define HIDDEN 128

typedef unsigned long long ull;

// ===================== PTX helpers =====================
__device__ __forceinline__ uint32_t smem_u32(const void* p) {
    uint32_t a;
    asm("{ .reg .u64 t; cvta.to.shared.u64 t, %1; cvt.u32.u64 %0, t; }"
        : "=r"(a) : "l"(p));
    return a;
}

#define LDSM_X4(r0, r1, r2, r3, addr) \
    asm volatile("ldmatrix.sync.aligned.m8n8.x4.shared.b16 {%0,%1,%2,%3}, [%4];" \
        : "=r"(r0), "=r"(r1), "=r"(r2), "=r"(r3) : "r"(addr))

#define LDSM_X4T(r0, r1, r2, r3, addr) \
    asm volatile("ldmatrix.sync.aligned.m8n8.x4.trans.shared.b16 {%0,%1,%2,%3}, [%4];" \
        : "=r"(r0), "=r"(r1), "=r"(r2), "=r"(r3) : "r"(addr))

#define MMA16816(c, a0, a1, a2, a3, b0, b1) \
    asm volatile("mma.sync.aligned.m16n8k16.row.col.f32.bf16.bf16.f32 " \
        "{%0,%1,%2,%3}, {%4,%5,%6,%7}, {%8,%9}, {%0,%1,%2,%3};" \
        : "+f"((c)[0]), "+f"((c)[1]), "+f"((c)[2]), "+f"((c)[3]) \
        : "r"(a0), "r"(a1), "r"(a2), "r"(a3), "r"(b0), "r"(b1))

#define CP_ASYNC16(dst, src) \
    asm volatile("cp.async.cg.shared.global [%0], [%1], 16;" \
        :: "r"(dst), "l"(src) : "memory")
#define CP_ASYNC_WAIT_ALL() \
    asm volatile("cp.async.commit_group;\n\tcp.async.wait_group 0;" ::: "memory")

__device__ __forceinline__ void split2(float a, float b, uint32_t& hp, uint32_t& lp) {
    __nv_bfloat16 h0 = __float2bfloat16(a);
    __nv_bfloat16 h1 = __float2bfloat16(b);
    __nv_bfloat16 l0 = __float2bfloat16(a - __bfloat162float(h0));
    __nv_bfloat16 l1 = __float2bfloat16(b - __bfloat162float(h1));
    hp = (uint32_t)__bfloat16_as_ushort(h0) | ((uint32_t)__bfloat16_as_ushort(h1) << 16);
    lp = (uint32_t)__bfloat16_as_ushort(l0) | ((uint32_t)__bfloat16_as_ushort(l1) << 16);
}

// scratch: xw = x @ W1 as bf16 hi/lo, [BATCH, N_NODE, 128] each (26.2 MB x2)
__device__ __nv_bfloat16 g_xwhi[(size_t)BATCH * N_NODE * HIDDEN];
__device__ __nv_bfloat16 g_xwlo[(size_t)BATCH * N_NODE * HIDDEN];
// W1 pre-split into bf16 hi/lo, zero-padded to K=208 rows: [208][128]
__device__ __nv_bfloat16 g_w1hi[208 * HIDDEN];
__device__ __nv_bfloat16 g_w1lo[208 * HIDDEN];

// ---------------------------------------------------------------------------
// K0: split W1 fp32 -> bf16 hi/lo with zero k-padding (runs once, tiny)
// ---------------------------------------------------------------------------
__global__ void split_w1_kernel(const float* __restrict__ W1)
{
    int idx = blockIdx.x * 256 + threadIdx.x;
    if (idx >= 208 * HIDDEN) return;
    int k = idx / HIDDEN;
    float v = (k < C_IN) ? W1[idx] : 0.f;
    __nv_bfloat16 h = __float2bfloat16(v);
    __nv_bfloat16 l = __float2bfloat16(v - __bfloat162float(h));
    g_w1hi[idx] = h;
    g_w1lo[idx] = l;
}

// ---------------------------------------------------------------------------
// K1: xw = x @ W1 via mma.sync split-bf16 (3 products: hh + hl + lh).
//   Output written directly as bf16 hi/lo (g_xwhi / g_xwlo).
// ---------------------------------------------------------------------------
#define K1_PA     432
#define K1_PB     272
#define K1_AHI    0
#define K1_ALO    55296
#define K1_BHI    110592
#define K1_BLO    167168
#define K1_SMEM   223744

__global__ __launch_bounds__(256, 1) void gemm_xw_mma_kernel(
    const float* __restrict__ x)
{
    extern __shared__ char smem[];
    const uint32_t sbase = smem_u32(smem);

    const int m0   = blockIdx.x * 128;
    const int t    = threadIdx.x;
    const int w    = t >> 5;
    const int lane = t & 31;

    // ---- issue B copies first (cp.async, overlapped with A conversion) ----
    for (int idx = t; idx < 208 * 16; idx += 256) {
        const int r = idx >> 4;
        const int c = idx & 15;
        CP_ASYNC16(sbase + K1_BHI + r * K1_PB + c * 16,
                   (const char*)g_w1hi + r * 256 + c * 16);
        CP_ASYNC16(sbase + K1_BLO + r * K1_PB + c * 16,
                   (const char*)g_w1lo + r * 256 + c * 16);
    }

    // ---- stage A: x tile [128 x 200] fp32 -> hi/lo bf16, pitch 432 ----
    for (int idx = t; idx < 128 * 50; idx += 256) {
        const int m = idx / 50;
        const int q = idx % 50;
        float4 v = *(const float4*)&x[(size_t)(m0 + m) * C_IN + q * 4];
        uint2 hp, lp;
        split2(v.x, v.y, hp.x, lp.x);
        split2(v.z, v.w, hp.y, lp.y);
        *(uint2*)(smem + K1_AHI + m * K1_PA + q * 8) = hp;
        *(uint2*)(smem + K1_ALO + m * K1_PA + q * 8) = lp;
    }
    // zero A k-pad (k = 200..207)
    if (t < 128) {
        *(uint4*)(smem + K1_AHI + t * K1_PA + 400) = make_uint4(0u, 0u, 0u, 0u);
        *(uint4*)(smem + K1_ALO + t * K1_PA + 400) = make_uint4(0u, 0u, 0u, 0u);
    }
    CP_ASYNC_WAIT_ALL();
    __syncthreads();

    // ---- MMA: warp w owns rows 16w..16w+15, all 128 n ----
    float acc[16][4];
#pragma unroll
    for (int n = 0; n < 16; n++) {
        acc[n][0] = 0.f; acc[n][1] = 0.f; acc[n][2] = 0.f; acc[n][3] = 0.f;
    }

    const uint32_t ah_base = sbase + K1_AHI
        + (uint32_t)(16 * w + (lane & 15)) * K1_PA + (uint32_t)(lane >> 4) * 16;
    const uint32_t al_base = ah_base + (K1_ALO - K1_AHI);
    const uint32_t b_off   = (uint32_t)(lane & 15) * K1_PB + (uint32_t)(lane >> 4) * 16;
    const uint32_t bhi_base = sbase + K1_BHI + b_off;
    const uint32_t blo_base = sbase + K1_BLO + b_off;

#pragma unroll 1
    for (int ks = 0; ks < 13; ks++) {
        uint32_t ah0, ah1, ah2, ah3, al0, al1, al2, al3;
        LDSM_X4(ah0, ah1, ah2, ah3, ah_base + (uint32_t)ks * 32);
        LDSM_X4(al0, al1, al2, al3, al_base + (uint32_t)ks * 32);
        const uint32_t brow = (uint32_t)ks * 16 * K1_PB;
#pragma unroll
        for (int nb = 0; nb < 8; nb++) {
            uint32_t h0, h1, h2, h3, l0, l1, l2, l3;
            LDSM_X4T(h0, h1, h2, h3, bhi_base + brow + (uint32_t)nb * 32);
            MMA16816(acc[2 * nb],     ah0, ah1, ah2, ah3, h0, h1);
            MMA16816(acc[2 * nb + 1], ah0, ah1, ah2, ah3, h2, h3);
            MMA16816(acc[2 * nb],     al0, al1, al2, al3, h0, h1);
            MMA16816(acc[2 * nb + 1], al0, al1, al2, al3, h2, h3);
            LDSM_X4T(l0, l1, l2, l3, blo_base + brow + (uint32_t)nb * 32);
            MMA16816(acc[2 * nb],     ah0, ah1, ah2, ah3, l0, l1);
            MMA16816(acc[2 * nb + 1], ah0, ah1, ah2, ah3, l2, l3);
        }
    }

    // ---- epilogue: split fragments to bf16 hi/lo and store ----
    const int g  = lane >> 2;
    const int tg = lane & 3;
    const size_t ra = (size_t)(m0 + 16 * w + g) * HIDDEN;
    const size_t rb = ra + 8 * HIDDEN;
    uint32_t* xh = (uint32_t*)g_xwhi;
    uint32_t* xl = (uint32_t*)g_xwlo;
#pragma unroll
    for (int nt = 0; nt < 16; nt++) {
        const int f = nt * 8 + tg * 2;
        uint32_t hp, lp;
        split2(acc[nt][0], acc[nt][1], hp, lp);
        xh[(ra + f) >> 1] = hp;
        xl[(ra + f) >> 1] = lp;
        split2(acc[nt][2], acc[nt][3], hp, lp);
        xh[(rb + f) >> 1] = hp;
        xl[(rb + f) >> 1] = lp;
    }
}

// ---------------------------------------------------------------------------
// K2: one CTA per batch, 512 threads, mma.sync m16n8k16 bf16 (split hi/lo B).
//   B staged by plain cp.async copies of g_xwhi/g_xwlo; targeted pad zeroing.
// ---------------------------------------------------------------------------
#define PITCH_A_B   432
#define PITCH_B_B   272
#define OFF_A       0
#define OFF_BHI     89856
#define OFF_BLO     146432
#define OFF_DEG     203008
#define OFF_PART    203840
#define OFF_W2S     205504
#define OFF_B1S     206528
#define SMEM_TOTAL  207040

__global__ __launch_bounds__(512, 1) void gin_fused_kernel(
    const int*   __restrict__ adj,
    const float* __restrict__ b1,
    const float* __restrict__ W2,
    const float* __restrict__ b2,
    const float* __restrict__ eps1p,
    const float* __restrict__ eps2p,
    float*       __restrict__ out)
{
    extern __shared__ char smem[];
    const uint32_t sbase = smem_u32(smem);
    float* degs = (float*)(smem + OFF_DEG);
    float* part = (float*)(smem + OFF_PART);
    float* w2s  = (float*)(smem + OFF_W2S);
    float* b1s  = (float*)(smem + OFF_B1S);

    const int b    = blockIdx.x;
    const int t    = threadIdx.x;
    const int w    = t >> 5;
    const int lane = t & 31;
    const int* adj_b = adj + (size_t)b * N_NODE * N_NODE;

    // ---- issue B copies first (cp.async), rows 0..199 of hi and lo ----
    {
        const char* srch = (const char*)g_xwhi + (size_t)b * N_NODE * 256;
        const char* srcl = (const char*)g_xwlo + (size_t)b * N_NODE * 256;
        for (int idx = t; idx < 200 * 16; idx += 512) {
            const int i = idx >> 4;
            const int c = idx & 15;
            CP_ASYNC16(sbase + OFF_BHI + i * PITCH_B_B + c * 16, srch + i * 256 + c * 16);
            CP_ASYNC16(sbase + OFF_BLO + i * PITCH_B_B + c * 16, srcl + i * 256 + c * 16);
        }
    }

    // ---- targeted pad zeroing ----
    {
        const uint4 z = make_uint4(0u, 0u, 0u, 0u);
        // A k-pad (k=200..207, 16B) for rows 0..199
        for (int r = t; r < 200; r += 512)
            *(uint4*)(smem + OFF_A + r * PITCH_A_B + 400) = z;
        // A pad rows 200..207: full 432B each (27 uint4)
        for (int idx = t; idx < 8 * 27; idx += 512) {
            const int r = 200 + idx / 27;
            const int c = idx % 27;
            *(uint4*)(smem + OFF_A + r * PITCH_A_B + c * 16) = z;
        }
        // B pad rows 200..207 (hi and lo), 16 uint4 each
        for (int idx = t; idx < 2 * 8 * 16; idx += 512) {
            const int buf = idx >> 7;
            const int r = 200 + ((idx >> 4) & 7);
            const int c = idx & 15;
            *(uint4*)(smem + (buf ? OFF_BLO : OFF_BHI) + r * PITCH_B_B + c * 16) = z;
        }
        if (t < 128) b1s[t] = b1[t];
        if (t < 256) w2s[t] = W2[t];
    }

    // ---- stage A: adjT[j][i] = adj[i][j] (transpose) + ROW degrees ----
    {
        for (int i = w; i < N_NODE; i += 16) {
            const int* row = &adj_b[i * N_NODE];
            int rsum = 0;
#pragma unroll
            for (int c = 0; c < 7; c++) {
                const int j = lane + 32 * c;
                if (j < N_NODE) {
                    int v = row[j];
                    *(unsigned short*)(smem + OFF_A + j * PITCH_A_B + i * 2) =
                        v ? (unsigned short)0x3F80u : (unsigned short)0u;
                    rsum += v;
                }
            }
#pragma unroll
            for (int off = 16; off; off >>= 1)
                rsum += __shfl_xor_sync(0xffffffffu, rsum, off);
            if (lane == 0) degs[i] = (float)rsum;
        }
    }
    CP_ASYNC_WAIT_ALL();
    __syncthreads();

    // ---- MMA + epilogue (warps 0..12; warp w owns rows 16w..16w+15) ----
    if (w < 13) {
        float acc[16][4];
#pragma unroll
        for (int n = 0; n < 16; n++) {
            acc[n][0] = 0.f; acc[n][1] = 0.f; acc[n][2] = 0.f; acc[n][3] = 0.f;
        }

        const uint32_t a_base = sbase + OFF_A
            + (uint32_t)(16 * w + (lane & 15)) * PITCH_A_B + (uint32_t)(lane >> 4) * 16;
        const uint32_t b_off = (uint32_t)(lane & 15) * PITCH_B_B + (uint32_t)(lane >> 4) * 16;
        const uint32_t bhi_base = sbase + OFF_BHI + b_off;
        const uint32_t blo_base = sbase + OFF_BLO + b_off;

#pragma unroll 1
        for (int ks = 0; ks < 13; ks++) {
            uint32_t a0, a1, a2, a3;
            LDSM_X4(a0, a1, a2, a3, a_base + (uint32_t)ks * 32);
            const uint32_t brow = (uint32_t)ks * 16 * PITCH_B_B;
#pragma unroll
            for (int nb = 0; nb < 8; nb++) {
                uint32_t h0, h1, h2, h3, l0, l1, l2, l3;
                LDSM_X4T(h0, h1, h2, h3, bhi_base + brow + (uint32_t)nb * 32);
                MMA16816(acc[2 * nb],     a0, a1, a2, a3, h0, h1);
                MMA16816(acc[2 * nb + 1], a0, a1, a2, a3, h2, h3);
                LDSM_X4T(l0, l1, l2, l3, blo_base + brow + (uint32_t)nb * 32);
                MMA16816(acc[2 * nb],     a0, a1, a2, a3, l0, l1);
                MMA16816(acc[2 * nb + 1], a0, a1, a2, a3, l2, l3);
            }
        }

        const float c1x = 1.f + *eps1p;
        const float c2x = 1.f + *eps2p;
        const int g  = lane >> 2;
        const int tg = lane & 3;
        const int ja = 16 * w + g;
        const int jb = ja + 8;

        float pa0 = 0.f, pa1 = 0.f, pb0 = 0.f, pb1 = 0.f;
#pragma unroll
        for (int nt = 0; nt < 16; nt++) {
            const int f0 = nt * 8 + tg * 2;
            uint32_t ha = *(uint32_t*)(smem + OFF_BHI + ja * PITCH_B_B + f0 * 2);
            uint32_t la = *(uint32_t*)(smem + OFF_BLO + ja * PITCH_B_B + f0 * 2);
            uint32_t hb = *(uint32_t*)(smem + OFF_BHI + jb * PITCH_B_B + f0 * 2);
            uint32_t lb = *(uint32_t*)(smem + OFF_BLO + jb * PITCH_B_B + f0 * 2);
            float xa0 = __uint_as_float(ha << 16) + __uint_as_float(la << 16);
            float xa1 = __uint_as_float(ha & 0xFFFF0000u) + __uint_as_float(la & 0xFFFF0000u);
            float xb0 = __uint_as_float(hb << 16) + __uint_as_float(lb << 16);
            float xb1 = __uint_as_float(hb & 0xFFFF0000u) + __uint_as_float(lb & 0xFFFF0000u);
            float bv0 = b1s[f0], bv1 = b1s[f0 + 1];
            float w00 = w2s[f0 * 2],       w01 = w2s[f0 * 2 + 1];
            float w10 = w2s[(f0 + 1) * 2], w11 = w2s[(f0 + 1) * 2 + 1];

            float ha0 = fmaxf(fmaf(c1x, xa0, acc[nt][0]) + bv0, 0.f);
            float ha1 = fmaxf(fmaf(c1x, xa1, acc[nt][1]) + bv1, 0.f);
            float hb0 = fmaxf(fmaf(c1x, xb0, acc[nt][2]) + bv0, 0.f);
            float hb1 = fmaxf(fmaf(c1x, xb1, acc[nt][3]) + bv1, 0.f);

            pa0 += ha0 * w00 + ha1 * w10;
            pa1 += ha0 * w01 + ha1 * w11;
            pb0 += hb0 * w00 + hb1 * w10;
            pb1 += hb0 * w01 + hb1 * w11;
        }
#pragma unroll
        for (int off = 1; off <= 2; off <<= 1) {
            pa0 += __shfl_xor_sync(0xffffffffu, pa0, off);
            pa1 += __shfl_xor_sync(0xffffffffu, pa1, off);
            pb0 += __shfl_xor_sync(0xffffffffu, pb0, off);
            pb1 += __shfl_xor_sync(0xffffffffu, pb1, off);
        }
        if (tg == 0) {
            float wa = (ja < N_NODE) ? (c2x + degs[ja]) : 0.f;
            float wb = (jb < N_NODE) ? (c2x + degs[jb]) : 0.f;
            part[ja * 2 + 0] = (ja < N_NODE) ? pa0 * wa : 0.f;
            part[ja * 2 + 1] = (ja < N_NODE) ? pa1 * wa : 0.f;
            part[jb * 2 + 0] = (jb < N_NODE) ? pb0 * wb : 0.f;
            part[jb * 2 + 1] = (jb < N_NODE) ? pb1 * wb : 0.f;
        }
    }
    __syncthreads();

    // ---- final graph reduction ----
    if (w == 0) {
        float s0 = 0.f, s1 = 0.f;
#pragma unroll
        for (int c = 0; c < 7; c++) {
            const int idx = lane + 32 * c;
            if (idx < N_NODE) { s0 += part[idx * 2 + 0]; s1 += part[idx * 2 + 1]; }
        }
#pragma unroll
        for (int off = 16; off; off >>= 1) {
            s0 += __shfl_xor_sync(0xffffffffu, s0, off);
            s1 += __shfl_xor_sync(0xffffffffu, s1, off);
        }
        if (lane == 0) {
            out[b * 2 + 0] = s0 * (1.f / N_NODE) + b2[0];
            out[b * 2 + 1] = s1 * (1.f / N_NODE) + b2[1];
        }
    }
}

// ---------------------------------------------------------------------------
extern "C" void kernel_launch(void* const* d_in, const int* in_sizes, int n_in,
                              void* d_out, int out_size)
{
    const float* x    = (const float*)d_in[0];   // [512,200,200]
    const int*   adj  = (const int*)  d_in[1];   // [512,200,200]
    const float* W1   = (const float*)d_in[2];   // [200,128]
    const float* b1   = (const float*)d_in[3];   // [128]
    const float* W2   = (const float*)d_in[4];   // [128,2]
    const float* b2   = (const float*)d_in[5];   // [2]
    const float* eps1 = (const float*)d_in[6];
    const float* eps2 = (const float*)d_in[7];
    float* out = (float*)d_out;                  // [512,2]

    cudaFuncSetAttribute(gemm_xw_mma_kernel,
                         cudaFuncAttributeMaxDynamicSharedMemorySize, K1_SMEM);
    cudaFuncSetAttribute(gin_fused_kernel,
                         cudaFuncAttributeMaxDynamicSharedMemorySize, SMEM_TOTAL);

    split_w1_kernel<<<(208 * HIDDEN + 255) / 256, 256>>>(W1);
    gemm_xw_mma_kernel<<<BATCH * N_NODE / 128, 256, K1_SMEM>>>(x);
    gin_fused_kernel<<<BATCH, 512, SMEM_TOTAL>>>(adj, b1, W2, b2, eps1, eps2, out);
}

// round 12
// speedup vs baseline: 3.1121x; 1.0551x over previous
#include <cuda_runtime.h>
#include <cuda_bf16.h>
#include <cstdint>

#define BATCH  512
#define N_NODE 200
#define C_IN   200
#define HIDDEN 128

typedef unsigned long long ull;

// ===================== PTX helpers =====================
__device__ __forceinline__ uint32_t smem_u32(const void* p) {
    uint32_t a;
    asm("{ .reg .u64 t; cvta.to.shared.u64 t, %1; cvt.u32.u64 %0, t; }"
        : "=r"(a) : "l"(p));
    return a;
}

#define LDSM_X4(r0, r1, r2, r3, addr) \
    asm volatile("ldmatrix.sync.aligned.m8n8.x4.shared.b16 {%0,%1,%2,%3}, [%4];" \
        : "=r"(r0), "=r"(r1), "=r"(r2), "=r"(r3) : "r"(addr))

#define LDSM_X4T(r0, r1, r2, r3, addr) \
    asm volatile("ldmatrix.sync.aligned.m8n8.x4.trans.shared.b16 {%0,%1,%2,%3}, [%4];" \
        : "=r"(r0), "=r"(r1), "=r"(r2), "=r"(r3) : "r"(addr))

#define MMA16816(c, a0, a1, a2, a3, b0, b1) \
    asm volatile("mma.sync.aligned.m16n8k16.row.col.f32.bf16.bf16.f32 " \
        "{%0,%1,%2,%3}, {%4,%5,%6,%7}, {%8,%9}, {%0,%1,%2,%3};" \
        : "+f"((c)[0]), "+f"((c)[1]), "+f"((c)[2]), "+f"((c)[3]) \
        : "r"(a0), "r"(a1), "r"(a2), "r"(a3), "r"(b0), "r"(b1))

#define CP_ASYNC16(dst, src) \
    asm volatile("cp.async.cg.shared.global [%0], [%1], 16;" \
        :: "r"(dst), "l"(src) : "memory")
#define CP_ASYNC_WAIT_ALL() \
    asm volatile("cp.async.commit_group;\n\tcp.async.wait_group 0;" ::: "memory")

__device__ __forceinline__ void split2(float a, float b, uint32_t& hp, uint32_t& lp) {
    __nv_bfloat16 h0 = __float2bfloat16(a);
    __nv_bfloat16 h1 = __float2bfloat16(b);
    __nv_bfloat16 l0 = __float2bfloat16(a - __bfloat162float(h0));
    __nv_bfloat16 l1 = __float2bfloat16(b - __bfloat162float(h1));
    hp = (uint32_t)__bfloat16_as_ushort(h0) | ((uint32_t)__bfloat16_as_ushort(h1) << 16);
    lp = (uint32_t)__bfloat16_as_ushort(l0) | ((uint32_t)__bfloat16_as_ushort(l1) << 16);
}

// scratch: xw = x @ W1 as bf16 hi/lo, [BATCH, N_NODE, 128] each
__device__ __nv_bfloat16 g_xwhi[(size_t)BATCH * N_NODE * HIDDEN];
__device__ __nv_bfloat16 g_xwlo[(size_t)BATCH * N_NODE * HIDDEN];
// W1 pre-split into bf16 hi/lo, zero-padded to K=208 rows: [208][128]
__device__ __nv_bfloat16 g_w1hi[208 * HIDDEN];
__device__ __nv_bfloat16 g_w1lo[208 * HIDDEN];

// ---------------------------------------------------------------------------
// K0: split W1 fp32 -> bf16 hi/lo with zero k-padding (runs once, tiny)
// ---------------------------------------------------------------------------
__global__ void split_w1_kernel(const float* __restrict__ W1)
{
    int idx = blockIdx.x * 256 + threadIdx.x;
    if (idx >= 208 * HIDDEN) return;
    int k = idx / HIDDEN;
    float v = (k < C_IN) ? W1[idx] : 0.f;
    __nv_bfloat16 h = __float2bfloat16(v);
    __nv_bfloat16 l = __float2bfloat16(v - __bfloat162float(h));
    g_w1hi[idx] = h;
    g_w1lo[idx] = l;
}

// ---------------------------------------------------------------------------
// K1: xw = x @ W1 via mma.sync split-bf16 (3 products: hh + hl + lh).
//   512 threads / 16 warps: warp = (m-tile w&7) x (n-half w>>3), m16 x n64.
// ---------------------------------------------------------------------------
#define K1_PA     432
#define K1_PB     272
#define K1_AHI    0
#define K1_ALO    55296
#define K1_BHI    110592
#define K1_BLO    167168
#define K1_SMEM   223744

__global__ __launch_bounds__(512, 1) void gemm_xw_mma_kernel(
    const float* __restrict__ x)
{
    extern __shared__ char smem[];
    const uint32_t sbase = smem_u32(smem);

    const int m0   = blockIdx.x * 128;
    const int t    = threadIdx.x;
    const int w    = t >> 5;
    const int lane = t & 31;

    // ---- issue B copies first (cp.async, overlapped with A conversion) ----
    for (int idx = t; idx < 208 * 16; idx += 512) {
        const int r = idx >> 4;
        const int c = idx & 15;
        CP_ASYNC16(sbase + K1_BHI + r * K1_PB + c * 16,
                   (const char*)g_w1hi + r * 256 + c * 16);
        CP_ASYNC16(sbase + K1_BLO + r * K1_PB + c * 16,
                   (const char*)g_w1lo + r * 256 + c * 16);
    }

    // ---- stage A: x tile [128 x 200] fp32 -> hi/lo bf16, pitch 432 ----
    for (int idx = t; idx < 128 * 50; idx += 512) {
        const int m = idx / 50;
        const int q = idx % 50;
        float4 v = *(const float4*)&x[(size_t)(m0 + m) * C_IN + q * 4];
        uint2 hp, lp;
        split2(v.x, v.y, hp.x, lp.x);
        split2(v.z, v.w, hp.y, lp.y);
        *(uint2*)(smem + K1_AHI + m * K1_PA + q * 8) = hp;
        *(uint2*)(smem + K1_ALO + m * K1_PA + q * 8) = lp;
    }
    // zero A k-pad (k = 200..207)
    if (t < 128) {
        *(uint4*)(smem + K1_AHI + t * K1_PA + 400) = make_uint4(0u, 0u, 0u, 0u);
        *(uint4*)(smem + K1_ALO + t * K1_PA + 400) = make_uint4(0u, 0u, 0u, 0u);
    }
    CP_ASYNC_WAIT_ALL();
    __syncthreads();

    // ---- MMA: warp = m-tile (w&7) x n-half (w>>3): rows 16mt.., cols 64nh.. ----
    const int mt = w & 7;
    const int nh = w >> 3;

    float acc[8][4];
#pragma unroll
    for (int n = 0; n < 8; n++) {
        acc[n][0] = 0.f; acc[n][1] = 0.f; acc[n][2] = 0.f; acc[n][3] = 0.f;
    }

    const uint32_t ah_base = sbase + K1_AHI
        + (uint32_t)(16 * mt + (lane & 15)) * K1_PA + (uint32_t)(lane >> 4) * 16;
    const uint32_t al_base = ah_base + (K1_ALO - K1_AHI);
    const uint32_t b_off   = (uint32_t)(lane & 15) * K1_PB + (uint32_t)(lane >> 4) * 16
                           + (uint32_t)nh * 128;
    const uint32_t bhi_base = sbase + K1_BHI + b_off;
    const uint32_t blo_base = sbase + K1_BLO + b_off;

#pragma unroll 1
    for (int ks = 0; ks < 13; ks++) {
        uint32_t ah0, ah1, ah2, ah3, al0, al1, al2, al3;
        LDSM_X4(ah0, ah1, ah2, ah3, ah_base + (uint32_t)ks * 32);
        LDSM_X4(al0, al1, al2, al3, al_base + (uint32_t)ks * 32);
        const uint32_t brow = (uint32_t)ks * 16 * K1_PB;
#pragma unroll
        for (int nb = 0; nb < 4; nb++) {
            uint32_t h0, h1, h2, h3, l0, l1, l2, l3;
            LDSM_X4T(h0, h1, h2, h3, bhi_base + brow + (uint32_t)nb * 32);
            MMA16816(acc[2 * nb],     ah0, ah1, ah2, ah3, h0, h1);
            MMA16816(acc[2 * nb + 1], ah0, ah1, ah2, ah3, h2, h3);
            MMA16816(acc[2 * nb],     al0, al1, al2, al3, h0, h1);
            MMA16816(acc[2 * nb + 1], al0, al1, al2, al3, h2, h3);
            LDSM_X4T(l0, l1, l2, l3, blo_base + brow + (uint32_t)nb * 32);
            MMA16816(acc[2 * nb],     ah0, ah1, ah2, ah3, l0, l1);
            MMA16816(acc[2 * nb + 1], ah0, ah1, ah2, ah3, l2, l3);
        }
    }

    // ---- epilogue: split fragments to bf16 hi/lo and store ----
    const int g  = lane >> 2;
    const int tg = lane & 3;
    const size_t ra = (size_t)(m0 + 16 * mt + g) * HIDDEN;
    const size_t rb = ra + 8 * HIDDEN;
    uint32_t* xh = (uint32_t*)g_xwhi;
    uint32_t* xl = (uint32_t*)g_xwlo;
#pragma unroll
    for (int nt = 0; nt < 8; nt++) {
        const int f = nh * 64 + nt * 8 + tg * 2;
        uint32_t hp, lp;
        split2(acc[nt][0], acc[nt][1], hp, lp);
        xh[(ra + f) >> 1] = hp;
        xl[(ra + f) >> 1] = lp;
        split2(acc[nt][2], acc[nt][3], hp, lp);
        xh[(rb + f) >> 1] = hp;
        xl[(rb + f) >> 1] = lp;
    }
}

// ---------------------------------------------------------------------------
// K2: one CTA per batch, 512 threads, mma.sync m16n8k16 bf16 (split hi/lo B).
//   adj staged NON-transposed [i][j] (contiguous stores); A fragments loaded
//   with ldmatrix.x4.trans (per-8x8 transpose == adjT fragment).
// ---------------------------------------------------------------------------
#define PITCH_A_B   432
#define PITCH_B_B   272
#define OFF_A       0
#define OFF_BHI     89856
#define OFF_BLO     146432
#define OFF_DEG     203008
#define OFF_PART    203840
#define OFF_W2S     205504
#define OFF_B1S     206528
#define SMEM_TOTAL  207040

__global__ __launch_bounds__(512, 1) void gin_fused_kernel(
    const int*   __restrict__ adj,
    const float* __restrict__ b1,
    const float* __restrict__ W2,
    const float* __restrict__ b2,
    const float* __restrict__ eps1p,
    const float* __restrict__ eps2p,
    float*       __restrict__ out)
{
    extern __shared__ char smem[];
    const uint32_t sbase = smem_u32(smem);
    float* degs = (float*)(smem + OFF_DEG);
    float* part = (float*)(smem + OFF_PART);
    float* w2s  = (float*)(smem + OFF_W2S);
    float* b1s  = (float*)(smem + OFF_B1S);

    const int b    = blockIdx.x;
    const int t    = threadIdx.x;
    const int w    = t >> 5;
    const int lane = t & 31;
    const int* adj_b = adj + (size_t)b * N_NODE * N_NODE;

    // ---- issue B copies first (cp.async), rows 0..199 of hi and lo ----
    {
        const char* srch = (const char*)g_xwhi + (size_t)b * N_NODE * 256;
        const char* srcl = (const char*)g_xwlo + (size_t)b * N_NODE * 256;
        for (int idx = t; idx < 200 * 16; idx += 512) {
            const int i = idx >> 4;
            const int c = idx & 15;
            CP_ASYNC16(sbase + OFF_BHI + i * PITCH_B_B + c * 16, srch + i * 256 + c * 16);
            CP_ASYNC16(sbase + OFF_BLO + i * PITCH_B_B + c * 16, srcl + i * 256 + c * 16);
        }
    }

    // ---- targeted pad zeroing ----
    {
        const uint4 z = make_uint4(0u, 0u, 0u, 0u);
        // A col-pad (j=200..207, 16B) for rows 0..199
        for (int r = t; r < 200; r += 512)
            *(uint4*)(smem + OFF_A + r * PITCH_A_B + 400) = z;
        // A pad rows 200..207 (k-pad): full 432B each (27 uint4)
        for (int idx = t; idx < 8 * 27; idx += 512) {
            const int r = 200 + idx / 27;
            const int c = idx % 27;
            *(uint4*)(smem + OFF_A + r * PITCH_A_B + c * 16) = z;
        }
        // B pad rows 200..207 (hi and lo), 16 uint4 each
        for (int idx = t; idx < 2 * 8 * 16; idx += 512) {
            const int buf = idx >> 7;
            const int r = 200 + ((idx >> 4) & 7);
            const int c = idx & 15;
            *(uint4*)(smem + (buf ? OFF_BLO : OFF_BHI) + r * PITCH_B_B + c * 16) = z;
        }
        if (t < 128) b1s[t] = b1[t];
        if (t < 256) w2s[t] = W2[t];
    }

    // ---- stage A: adj[i][j] NON-transposed (contiguous stores) + ROW degs ----
    {
        for (int i = w; i < N_NODE; i += 16) {
            const int* row = &adj_b[i * N_NODE];
            char* dst = smem + OFF_A + i * PITCH_A_B;
            int rsum = 0;
#pragma unroll
            for (int c = 0; c < 7; c++) {
                const int j = lane + 32 * c;
                if (j < N_NODE) {
                    int v = row[j];
                    *(unsigned short*)(dst + j * 2) =
                        v ? (unsigned short)0x3F80u : (unsigned short)0u;
                    rsum += v;
                }
            }
#pragma unroll
            for (int off = 16; off; off >>= 1)
                rsum += __shfl_xor_sync(0xffffffffu, rsum, off);
            if (lane == 0) degs[i] = (float)rsum;
        }
    }
    CP_ASYNC_WAIT_ALL();
    __syncthreads();

    // ---- MMA + epilogue (warps 0..12; warp w owns out-rows j=16w..16w+15) ----
    if (w < 13) {
        float acc[16][4];
#pragma unroll
        for (int n = 0; n < 16; n++) {
            acc[n][0] = 0.f; acc[n][1] = 0.f; acc[n][2] = 0.f; acc[n][3] = 0.f;
        }

        // A via ldmatrix.trans from S[i][j]: lane -> S row i0+(l&7)+((l>>4)<<3),
        // col j0 + ((l>>3)&1)*8   (j0 = 16w)
        const uint32_t a_base = sbase + OFF_A
            + (uint32_t)((lane & 7) + ((lane >> 4) << 3)) * PITCH_A_B
            + (uint32_t)(16 * w + ((lane >> 3) & 1) * 8) * 2;
        const uint32_t b_off = (uint32_t)(lane & 15) * PITCH_B_B + (uint32_t)(lane >> 4) * 16;
        const uint32_t bhi_base = sbase + OFF_BHI + b_off;
        const uint32_t blo_base = sbase + OFF_BLO + b_off;

#pragma unroll 1
        for (int ks = 0; ks < 13; ks++) {
            uint32_t a0, a1, a2, a3;
            LDSM_X4T(a0, a1, a2, a3, a_base + (uint32_t)ks * 16 * PITCH_A_B);
            const uint32_t brow = (uint32_t)ks * 16 * PITCH_B_B;
#pragma unroll
            for (int nb = 0; nb < 8; nb++) {
                uint32_t h0, h1, h2, h3, l0, l1, l2, l3;
                LDSM_X4T(h0, h1, h2, h3, bhi_base + brow + (uint32_t)nb * 32);
                MMA16816(acc[2 * nb],     a0, a1, a2, a3, h0, h1);
                MMA16816(acc[2 * nb + 1], a0, a1, a2, a3, h2, h3);
                LDSM_X4T(l0, l1, l2, l3, blo_base + brow + (uint32_t)nb * 32);
                MMA16816(acc[2 * nb],     a0, a1, a2, a3, l0, l1);
                MMA16816(acc[2 * nb + 1], a0, a1, a2, a3, l2, l3);
            }
        }

        const float c1x = 1.f + *eps1p;
        const float c2x = 1.f + *eps2p;
        const int g  = lane >> 2;
        const int tg = lane & 3;
        const int ja = 16 * w + g;
        const int jb = ja + 8;

        float pa0 = 0.f, pa1 = 0.f, pb0 = 0.f, pb1 = 0.f;
#pragma unroll
        for (int nt = 0; nt < 16; nt++) {
            const int f0 = nt * 8 + tg * 2;
            uint32_t ha = *(uint32_t*)(smem + OFF_BHI + ja * PITCH_B_B + f0 * 2);
            uint32_t la = *(uint32_t*)(smem + OFF_BLO + ja * PITCH_B_B + f0 * 2);
            uint32_t hb = *(uint32_t*)(smem + OFF_BHI + jb * PITCH_B_B + f0 * 2);
            uint32_t lb = *(uint32_t*)(smem + OFF_BLO + jb * PITCH_B_B + f0 * 2);
            float xa0 = __uint_as_float(ha << 16) + __uint_as_float(la << 16);
            float xa1 = __uint_as_float(ha & 0xFFFF0000u) + __uint_as_float(la & 0xFFFF0000u);
            float xb0 = __uint_as_float(hb << 16) + __uint_as_float(lb << 16);
            float xb1 = __uint_as_float(hb & 0xFFFF0000u) + __uint_as_float(lb & 0xFFFF0000u);
            float bv0 = b1s[f0], bv1 = b1s[f0 + 1];
            float w00 = w2s[f0 * 2],       w01 = w2s[f0 * 2 + 1];
            float w10 = w2s[(f0 + 1) * 2], w11 = w2s[(f0 + 1) * 2 + 1];

            float ha0 = fmaxf(fmaf(c1x, xa0, acc[nt][0]) + bv0, 0.f);
            float ha1 = fmaxf(fmaf(c1x, xa1, acc[nt][1]) + bv1, 0.f);
            float hb0 = fmaxf(fmaf(c1x, xb0, acc[nt][2]) + bv0, 0.f);
            float hb1 = fmaxf(fmaf(c1x, xb1, acc[nt][3]) + bv1, 0.f);

            pa0 += ha0 * w00 + ha1 * w10;
            pa1 += ha0 * w01 + ha1 * w11;
            pb0 += hb0 * w00 + hb1 * w10;
            pb1 += hb0 * w01 + hb1 * w11;
        }
#pragma unroll
        for (int off = 1; off <= 2; off <<= 1) {
            pa0 += __shfl_xor_sync(0xffffffffu, pa0, off);
            pa1 += __shfl_xor_sync(0xffffffffu, pa1, off);
            pb0 += __shfl_xor_sync(0xffffffffu, pb0, off);
            pb1 += __shfl_xor_sync(0xffffffffu, pb1, off);
        }
        if (tg == 0) {
            float wa = (ja < N_NODE) ? (c2x + degs[ja]) : 0.f;
            float wb = (jb < N_NODE) ? (c2x + degs[jb]) : 0.f;
            part[ja * 2 + 0] = (ja < N_NODE) ? pa0 * wa : 0.f;
            part[ja * 2 + 1] = (ja < N_NODE) ? pa1 * wa : 0.f;
            part[jb * 2 + 0] = (jb < N_NODE) ? pb0 * wb : 0.f;
            part[jb * 2 + 1] = (jb < N_NODE) ? pb1 * wb : 0.f;
        }
    }
    __syncthreads();

    // ---- final graph reduction ----
    if (w == 0) {
        float s0 = 0.f, s1 = 0.f;
#pragma unroll
        for (int c = 0; c < 7; c++) {
            const int idx = lane + 32 * c;
            if (idx < N_NODE) { s0 += part[idx * 2 + 0]; s1 += part[idx * 2 + 1]; }
        }
#pragma unroll
        for (int off = 16; off; off >>= 1) {
            s0 += __shfl_xor_sync(0xffffffffu, s0, off);
            s1 += __shfl_xor_sync(0xffffffffu, s1, off);
        }
        if (lane == 0) {
            out[b * 2 + 0] = s0 * (1.f / N_NODE) + b2[0];
            out[b * 2 + 1] = s1 * (1.f / N_NODE) + b2[1];
        }
    }
}

// ---------------------------------------------------------------------------
extern "C" void kernel_launch(void* const* d_in, const int* in_sizes, int n_in,
                              void* d_out, int out_size)
{
    const float* x    = (const float*)d_in[0];   // [512,200,200]
    const int*   adj  = (const int*)  d_in[1];   // [512,200,200]
    const float* W1   = (const float*)d_in[2];   // [200,128]
    const float* b1   = (const float*)d_in[3];   // [128]
    const float* W2   = (const float*)d_in[4];   // [128,2]
    const float* b2   = (const float*)d_in[5];   // [2]
    const float* eps1 = (const float*)d_in[6];
    const float* eps2 = (const float*)d_in[7];
    float* out = (float*)d_out;                  // [512,2]

    cudaFuncSetAttribute(gemm_xw_mma_kernel,
                         cudaFuncAttributeMaxDynamicSharedMemorySize, K1_SMEM);
    cudaFuncSetAttribute(gin_fused_kernel,
                         cudaFuncAttributeMaxDynamicSharedMemorySize, SMEM_TOTAL);

    split_w1_kernel<<<(208 * HIDDEN + 255) / 256, 256>>>(W1);
    gemm_xw_mma_kernel<<<BATCH * N_NODE / 128, 512, K1_SMEM>>>(x);
    gin_fused_kernel<<<BATCH, 512, SMEM_TOTAL>>>(adj, b1, W2, b2, eps1, eps2, out);
}